// round 13
// baseline (speedup 1.0000x reference)
#include <cuda_runtime.h>
#include <cuda_bf16.h>
#include <cuda_fp16.h>
#include <math.h>
#include <stdint.h>

// ---------------- problem constants ----------------
#define Bb 32
#define Tt 256
#define Ss 16
#define Ee 400
#define Hh 400
#define HC 200
#define NHd 20
#define DHd 20
#define NTOK (Bb*Tt*Ss)   // 131072
#define NBT  (Bb*Tt)      // 8192
#define KP1 416           // padded K for K=400 (13 chunks of 32)

// ---------------- scratch ----------------
__device__ __half g_qkh[(size_t)NTOK*800];   // fp16 q|k
__device__ float g_xg[(size_t)NBT*1600];
__device__ float g_pooled[(size_t)NBT*Ee];
__device__ float g_h[(size_t)NBT*Hh];        // zero-init; rows t>=L stay 0
__device__ float g_cat[(size_t)NBT*2*Hh];
__device__ uint2 g_wpkh_f[HC*HC];            // fp16 packed w_hh
__device__ uint2 g_wpkh_b[HC*HC];
__device__ float g_bqk[800];
__device__ float g_bsum_cat[1600];

// ---------------- bf16 hi/lo planes (zero-init => padding stays 0) ----------------
__device__ __nv_bfloat16 g_x2h[(size_t)NTOK*KP1];
__device__ __nv_bfloat16 g_x2l[(size_t)NTOK*KP1];
__device__ __nv_bfloat16 g_x1h[(size_t)NBT*KP1];
__device__ __nv_bfloat16 g_x1l[(size_t)NBT*KP1];
__device__ __nv_bfloat16 g_plh[(size_t)NBT*KP1];
__device__ __nv_bfloat16 g_pll[(size_t)NBT*KP1];
__device__ __nv_bfloat16 g_cth[(size_t)NBT*800];
__device__ __nv_bfloat16 g_ctl[(size_t)NBT*800];
__device__ __nv_bfloat16 g_wqkh[896*KP1];
__device__ __nv_bfloat16 g_wqkl[896*KP1];
__device__ __nv_bfloat16 g_wihh[1664*KP1];
__device__ __nv_bfloat16 g_wihl[1664*KP1];
__device__ __nv_bfloat16 g_wmhah[512*KP1];
__device__ __nv_bfloat16 g_wmhal[512*KP1];
__device__ __nv_bfloat16 g_wmlph[512*800];
__device__ __nv_bfloat16 g_wmlpl[512*800];

// =================== common helpers ===================
__device__ __forceinline__ uint32_t smem_to_u32(const void* p) {
    uint32_t a;
    asm("{ .reg .u64 t; cvta.to.shared.u64 t, %1; cvt.u32.u64 %0, t; }" : "=r"(a) : "l"(p));
    return a;
}
__device__ __forceinline__ void cp_async16(uint32_t saddr, const void* gaddr) {
    asm volatile("cp.async.cg.shared.global [%0], [%1], 16;" :: "r"(saddr), "l"(gaddr));
}
#define CP_COMMIT() asm volatile("cp.async.commit_group;" ::: "memory")
#define CP_WAIT(n)  asm volatile("cp.async.wait_group %0;" :: "n"(n) : "memory")

__device__ __forceinline__ void split4_store(float4 v, __nv_bfloat16* hp, __nv_bfloat16* lp) {
    __nv_bfloat16 h0 = __float2bfloat16(v.x);
    __nv_bfloat16 h1 = __float2bfloat16(v.y);
    __nv_bfloat16 h2 = __float2bfloat16(v.z);
    __nv_bfloat16 h3 = __float2bfloat16(v.w);
    __nv_bfloat16 l0 = __float2bfloat16(v.x - __bfloat162float(h0));
    __nv_bfloat16 l1 = __float2bfloat16(v.y - __bfloat162float(h1));
    __nv_bfloat16 l2 = __float2bfloat16(v.z - __bfloat162float(h2));
    __nv_bfloat16 l3 = __float2bfloat16(v.w - __bfloat162float(h3));
    uint2 hv, lv;
    hv.x = (uint32_t)__bfloat16_as_ushort(h0) | ((uint32_t)__bfloat16_as_ushort(h1) << 16);
    hv.y = (uint32_t)__bfloat16_as_ushort(h2) | ((uint32_t)__bfloat16_as_ushort(h3) << 16);
    lv.x = (uint32_t)__bfloat16_as_ushort(l0) | ((uint32_t)__bfloat16_as_ushort(l1) << 16);
    lv.y = (uint32_t)__bfloat16_as_ushort(l2) | ((uint32_t)__bfloat16_as_ushort(l3) << 16);
    *reinterpret_cast<uint2*>(hp) = hv;
    *reinterpret_cast<uint2*>(lp) = lv;
}

// =================== split: fp32 -> bf16 hi/lo planes ===================
__global__ void split_kernel(const float* __restrict__ src, __nv_bfloat16* __restrict__ dh,
                             __nv_bfloat16* __restrict__ dl, int M, int K, int Kp)
{
    const int kq = K >> 2;
    const int nv = M * kq;
    for (int i = blockIdx.x * blockDim.x + threadIdx.x; i < nv; i += gridDim.x * blockDim.x) {
        int row = i / kq;
        int c4 = (i - row * kq) * 4;
        float4 v = reinterpret_cast<const float4*>(src)[i];
        size_t off = (size_t)row * Kp + c4;
        split4_store(v, dh + off, dl + off);
    }
}

// =================== prep_qk: ONLY what the q|k GEMM needs ===================
__global__ void prep_qk_kernel(const float* __restrict__ w_q, const float* __restrict__ b_q,
                               const float* __restrict__ w_k, const float* __restrict__ b_k)
{
    const int gt = blockIdx.x * blockDim.x + threadIdx.x;
    const int gs = gridDim.x * blockDim.x;
    if (gt < 800) g_bqk[gt] = (gt < 400) ? b_q[gt] : b_k[gt - 400];
    for (int idx = gt; idx < 800 * 100; idx += gs) {
        int row = idx / 100, q4 = (idx - row * 100) * 4;
        const float* src = (row < 400) ? (w_q + (size_t)row * 400) : (w_k + (size_t)(row - 400) * 400);
        float4 v = *reinterpret_cast<const float4*>(src + q4);
        size_t off = (size_t)row * KP1 + q4;
        split4_store(v, g_wqkh + off, g_wqkl + off);
    }
}

// =================== prep_rest: biases + fp16 packed w_hh + other weight planes ===================
__global__ void prep_rest_kernel(const float* __restrict__ b_ih_f, const float* __restrict__ b_hh_f,
                                 const float* __restrict__ b_ih_b, const float* __restrict__ b_hh_b,
                                 const float* __restrict__ w_hh_f, const float* __restrict__ w_hh_b,
                                 const float* __restrict__ w_ih_f, const float* __restrict__ w_ih_b,
                                 const float* __restrict__ w_mlp_mha, const float* __restrict__ w_mlp)
{
    const int gt = blockIdx.x * blockDim.x + threadIdx.x;
    const int gs = gridDim.x * blockDim.x;

    if (gt < 1600) g_bsum_cat[gt] = (gt < 800) ? (b_ih_f[gt] + b_hh_f[gt])
                                               : (b_ih_b[gt - 800] + b_hh_b[gt - 800]);

    for (int idx = gt; idx < 1600 * 100; idx += gs) {
        int row = idx / 100, q4 = (idx - row * 100) * 4;
        const float* src = (row < 800) ? (w_ih_f + (size_t)row * 400) : (w_ih_b + (size_t)(row - 800) * 400);
        float4 v = *reinterpret_cast<const float4*>(src + q4);
        size_t off = (size_t)row * KP1 + q4;
        split4_store(v, g_wihh + off, g_wihl + off);
    }
    for (int idx = gt; idx < 400 * 100; idx += gs) {
        int row = idx / 100, q4 = (idx - row * 100) * 4;
        float4 v = *reinterpret_cast<const float4*>(w_mlp_mha + (size_t)row * 400 + q4);
        size_t off = (size_t)row * KP1 + q4;
        split4_store(v, g_wmhah + off, g_wmhal + off);
    }
    for (int idx = gt; idx < 400 * 200; idx += gs) {
        int row = idx / 200, q4 = (idx - row * 200) * 4;
        float4 v = *reinterpret_cast<const float4*>(w_mlp + (size_t)row * 800 + q4);
        size_t off = (size_t)row * 800 + q4;
        split4_store(v, g_wmlph + off, g_wmlpl + off);
    }
    for (int idx = gt; idx < HC * HC; idx += gs) {
        int k = idx / HC, u = idx % HC;
        {
            __half2 p0 = __floats2half2_rn(w_hh_f[(size_t)u * HC + k],          w_hh_f[(size_t)(HC + u) * HC + k]);
            __half2 p1 = __floats2half2_rn(w_hh_f[(size_t)(2*HC + u) * HC + k], w_hh_f[(size_t)(3*HC + u) * HC + k]);
            uint2 w;
            w.x = *reinterpret_cast<uint32_t*>(&p0);
            w.y = *reinterpret_cast<uint32_t*>(&p1);
            g_wpkh_f[idx] = w;
        }
        {
            __half2 p0 = __floats2half2_rn(w_hh_b[(size_t)u * HC + k],          w_hh_b[(size_t)(HC + u) * HC + k]);
            __half2 p1 = __floats2half2_rn(w_hh_b[(size_t)(2*HC + u) * HC + k], w_hh_b[(size_t)(3*HC + u) * HC + k]);
            uint2 w;
            w.x = *reinterpret_cast<uint32_t*>(&p0);
            w.y = *reinterpret_cast<uint32_t*>(&p1);
            g_wpkh_b[idx] = w;
        }
    }
}

// =================== bf16x3 mma.sync GEMM, pre-split operands, cp.async ===================
#define BKC 32
#define LDK 40
#define TILE_ELE (128*LDK)
#define TILE_B   (TILE_ELE*2)
#define STAGE_BYTES (4*TILE_B)
#define GEMM_SMEM (2*STAGE_BYTES + 512)
#define OFFB_AHI 0
#define OFFB_ALO TILE_B
#define OFFB_WHI (2*TILE_B)
#define OFFB_WLO (3*TILE_B)

#define MMA16816(d, a, b) \
    asm volatile("mma.sync.aligned.m16n8k16.row.col.f32.bf16.bf16.f32 " \
        "{%0,%1,%2,%3}, {%4,%5,%6,%7}, {%8,%9}, {%0,%1,%2,%3};" \
        : "+f"((d)[0]), "+f"((d)[1]), "+f"((d)[2]), "+f"((d)[3]) \
        : "r"((a)[0]), "r"((a)[1]), "r"((a)[2]), "r"((a)[3]), "r"((b)[0]), "r"((b)[1]))

#define LDSM4(r0, r1, r2, r3, addr) \
    asm volatile("ldmatrix.sync.aligned.m8n8.x4.shared.b16 {%0,%1,%2,%3}, [%4];" \
        : "=r"(r0), "=r"(r1), "=r"(r2), "=r"(r3) : "r"(addr))

__global__ void __launch_bounds__(256, 2)
tc_gemm2(const __nv_bfloat16* __restrict__ Ahi, const __nv_bfloat16* __restrict__ Alo,
         const __nv_bfloat16* __restrict__ Whi, const __nv_bfloat16* __restrict__ Wlo,
         const float* __restrict__ bias, float* __restrict__ C, __half* __restrict__ Ch,
         const int* __restrict__ mlens,
         int N, int Kp, int NC, int ldc)
{
    extern __shared__ __align__(1024) char smem[];
    const uint32_t sbu = smem_to_u32(smem);
    float* bsm = reinterpret_cast<float*>(smem + 2 * STAGE_BYTES);

    const int tid = threadIdx.x;
    const int lane = tid & 31, wid = tid >> 5;
    const int wm = wid & 3, wn = wid >> 2;
    const int m0 = blockIdx.y * 128;
    const int n0 = blockIdx.x * 128;

    const int rem = (N - n0) - wn * 64;
    const int ntmax = (rem >= 64) ? 8 : ((rem <= 0) ? 0 : ((rem + 7) >> 3));
    const int npair = (ntmax + 1) >> 1;

    const int crow = tid >> 2;
    const int cq = (tid & 3) * 8;
    const __nv_bfloat16* sAh0 = Ahi + (size_t)(m0 + crow) * Kp + cq;
    const __nv_bfloat16* sAh1 = Ahi + (size_t)(m0 + crow + 64) * Kp + cq;
    const __nv_bfloat16* sAl0 = Alo + (size_t)(m0 + crow) * Kp + cq;
    const __nv_bfloat16* sAl1 = Alo + (size_t)(m0 + crow + 64) * Kp + cq;
    const __nv_bfloat16* sWh0 = Whi + (size_t)(n0 + crow) * Kp + cq;
    const __nv_bfloat16* sWh1 = Whi + (size_t)(n0 + crow + 64) * Kp + cq;
    const __nv_bfloat16* sWl0 = Wlo + (size_t)(n0 + crow) * Kp + cq;
    const __nv_bfloat16* sWl1 = Wlo + (size_t)(n0 + crow + 64) * Kp + cq;
    const uint32_t doff0 = (uint32_t)((crow * LDK + cq) * 2);
    const uint32_t doff1 = (uint32_t)(((crow + 64) * LDK + cq) * 2);

    const int ro = lane & 15;
    const int khalf = (lane >> 4) << 3;
    const uint32_t aoff0 = (uint32_t)(((wm * 32 + ro) * LDK + khalf) * 2);
    const uint32_t aoff1 = aoff0 + 16 * LDK * 2;
    uint32_t boff[4];
    #pragma unroll
    for (int p = 0; p < 4; p++)
        boff[p] = (uint32_t)(((wn * 64 + p * 16 + ro) * LDK + khalf) * 2);

    if (tid < 128) bsm[tid] = (n0 + tid < N) ? bias[n0 + tid] : 0.f;

    float acc[2][8][4];
    #pragma unroll
    for (int i = 0; i < 2; i++)
        #pragma unroll
        for (int j = 0; j < 8; j++)
            #pragma unroll
            for (int q = 0; q < 4; q++) acc[i][j][q] = 0.f;

    #define ISSUE_CHUNK(cc, st) do { \
        const int _k0 = (cc) * BKC; \
        const uint32_t _db = sbu + (st) * STAGE_BYTES; \
        cp_async16(_db + OFFB_AHI + doff0, sAh0 + _k0); \
        cp_async16(_db + OFFB_AHI + doff1, sAh1 + _k0); \
        cp_async16(_db + OFFB_ALO + doff0, sAl0 + _k0); \
        cp_async16(_db + OFFB_ALO + doff1, sAl1 + _k0); \
        cp_async16(_db + OFFB_WHI + doff0, sWh0 + _k0); \
        cp_async16(_db + OFFB_WHI + doff1, sWh1 + _k0); \
        cp_async16(_db + OFFB_WLO + doff0, sWl0 + _k0); \
        cp_async16(_db + OFFB_WLO + doff1, sWl1 + _k0); \
    } while (0)

    ISSUE_CHUNK(0, 0);
    CP_COMMIT();

    for (int c = 0; c < NC; c++) {
        if (c + 1 < NC) {
            ISSUE_CHUNK(c + 1, (c + 1) & 1);
            CP_COMMIT();
            CP_WAIT(1);
        } else {
            CP_WAIT(0);
        }
        __syncthreads();

        if (npair > 0) {
            const uint32_t base = sbu + (c & 1) * STAGE_BYTES;
            #pragma unroll
            for (int ks = 0; ks < 2; ks++) {
                const uint32_t kb = base + ks * 32;
                uint32_t ah[2][4], al[2][4];
                LDSM4(ah[0][0], ah[0][1], ah[0][2], ah[0][3], kb + OFFB_AHI + aoff0);
                LDSM4(ah[1][0], ah[1][1], ah[1][2], ah[1][3], kb + OFFB_AHI + aoff1);
                LDSM4(al[0][0], al[0][1], al[0][2], al[0][3], kb + OFFB_ALO + aoff0);
                LDSM4(al[1][0], al[1][1], al[1][2], al[1][3], kb + OFFB_ALO + aoff1);
                #pragma unroll
                for (int p = 0; p < 4; p++) {
                    if (p < npair) {
                        uint32_t u0, u1, u2, u3;
                        LDSM4(u0, u1, u2, u3, kb + OFFB_WHI + boff[p]);
                        uint32_t f0[2] = {u0, u2};
                        uint32_t f1[2] = {u1, u3};
                        MMA16816(acc[0][2*p],   ah[0], f0);
                        MMA16816(acc[1][2*p],   ah[1], f0);
                        MMA16816(acc[0][2*p+1], ah[0], f1);
                        MMA16816(acc[1][2*p+1], ah[1], f1);
                        MMA16816(acc[0][2*p],   al[0], f0);
                        MMA16816(acc[1][2*p],   al[1], f0);
                        MMA16816(acc[0][2*p+1], al[0], f1);
                        MMA16816(acc[1][2*p+1], al[1], f1);
                        LDSM4(u0, u1, u2, u3, kb + OFFB_WLO + boff[p]);
                        uint32_t g0[2] = {u0, u2};
                        uint32_t g1[2] = {u1, u3};
                        MMA16816(acc[0][2*p],   ah[0], g0);
                        MMA16816(acc[1][2*p],   ah[1], g0);
                        MMA16816(acc[0][2*p+1], ah[0], g1);
                        MMA16816(acc[1][2*p+1], ah[1], g1);
                    }
                }
            }
        }
        __syncthreads();
    }

    const int g = lane >> 2, t = lane & 3;
    #pragma unroll
    for (int mt = 0; mt < 2; mt++) {
        int row_a = m0 + wm * 32 + mt * 16 + g;
        int row_b = row_a + 8;
        if (Ch) {
            __half* ca = Ch + (size_t)row_a * ldc;
            __half* cb = Ch + (size_t)row_b * ldc;
            #pragma unroll
            for (int nt = 0; nt < 8; nt++) {
                int lc = wn * 64 + nt * 8 + 2 * t;
                int n = n0 + lc;
                if (n < N) {
                    float b0 = bsm[lc], b1 = bsm[lc + 1];
                    __half2 v0 = __floats2half2_rn(acc[mt][nt][0] + b0, acc[mt][nt][1] + b1);
                    __half2 v1 = __floats2half2_rn(acc[mt][nt][2] + b0, acc[mt][nt][3] + b1);
                    *reinterpret_cast<__half2*>(ca + n) = v0;
                    *reinterpret_cast<__half2*>(cb + n) = v1;
                }
            }
        } else {
            float va = 1.f, vb = 1.f;
            if (mlens) {
                va = ((row_a & (Tt - 1)) < mlens[row_a >> 8]) ? 1.f : 0.f;
                vb = ((row_b & (Tt - 1)) < mlens[row_b >> 8]) ? 1.f : 0.f;
            }
            float* ca = C + (size_t)row_a * ldc;
            float* cb = C + (size_t)row_b * ldc;
            #pragma unroll
            for (int nt = 0; nt < 8; nt++) {
                int lc = wn * 64 + nt * 8 + 2 * t;
                int n = n0 + lc;
                if (n < N) {
                    float b0 = bsm[lc], b1 = bsm[lc + 1];
                    *reinterpret_cast<float2*>(ca + n) = make_float2((acc[mt][nt][0] + b0) * va, (acc[mt][nt][1] + b1) * va);
                    *reinterpret_cast<float2*>(cb + n) = make_float2((acc[mt][nt][2] + b0) * vb, (acc[mt][nt][3] + b1) * vb);
                }
            }
        }
    }
}

// ---------------- per-news MHA pooling (fp16 q|k input, float2 dots) ----------------
#define PEE 402
__global__ void __launch_bounds__(256)
pool_kernel(const float* __restrict__ x2)
{
    extern __shared__ float sm[];
    float* qs = sm;
    float* ks = sm + Ss * PEE;
    float* msm = sm + 2 * Ss * PEE;
    float* wf  = msm + Ss;
    const int n = blockIdx.x;
    const int tid = threadIdx.x;
    const int lane = tid & 31, warp = tid >> 5;

    for (int i = tid; i < Ss * Ee; i += 256) {
        int row = i / Ee, col = i % Ee;
        const __half* src = g_qkh + (size_t)(n * Ss + row) * 800;
        qs[row * PEE + col] = __half2float(src[col]);
        ks[row * PEE + col] = __half2float(src[400 + col]);
    }
    __syncthreads();

    const float scale = rsqrtf((float)DHd);
    const int half = lane >> 4;
    const int kl = lane & 15;

    #pragma unroll
    for (int rep = 0; rep < 2; rep++) {
        const int qi = warp + 8 * rep;
        float accw = 0.f;
        const float* kp_base = ks + kl * PEE;
        const float* qp_base = qs + qi * PEE;
        #pragma unroll
        for (int hh = 0; hh < 10; hh++) {
            int h = 2 * hh + half;
            const float2* qp2 = reinterpret_cast<const float2*>(qp_base + h * DHd);
            const float2* kp2 = reinterpret_cast<const float2*>(kp_base + h * DHd);
            float s = 0.f;
            #pragma unroll
            for (int d = 0; d < 10; d++) {
                float2 a = qp2[d], b = kp2[d];
                s = fmaf(a.x, b.x, s);
                s = fmaf(a.y, b.y, s);
            }
            s *= scale;
            float mx = s;
            #pragma unroll
            for (int o = 8; o; o >>= 1) mx = fmaxf(mx, __shfl_xor_sync(0xffffffffu, mx, o));
            float e = expf(s - mx);
            float sum = e;
            #pragma unroll
            for (int o = 8; o; o >>= 1) sum += __shfl_xor_sync(0xffffffffu, sum, o);
            accw += e / (sum * (float)NHd);
        }
        accw += __shfl_xor_sync(0xffffffffu, accw, 16);
        float tot = accw;
        #pragma unroll
        for (int o = 8; o; o >>= 1) tot += __shfl_xor_sync(0xffffffffu, tot, o);
        if (lane == 0) msm[qi] = tot * (1.f / (float)Ss);
    }
    __syncthreads();

    if (warp == 0) {
        float v = (lane < Ss) ? msm[lane] : -1e30f;
        float mx = v;
        #pragma unroll
        for (int o = 8; o; o >>= 1) mx = fmaxf(mx, __shfl_xor_sync(0xffffffffu, mx, o));
        mx = fmaxf(mx, __shfl_xor_sync(0xffffffffu, mx, 16));
        float e = (lane < Ss) ? expf(v - mx) : 0.f;
        float z = e;
        #pragma unroll
        for (int o = 8; o; o >>= 1) z += __shfl_xor_sync(0xffffffffu, z, o);
        z += __shfl_xor_sync(0xffffffffu, z, 16);
        if (lane < Ss) wf[lane] = e / z;
    }
    __syncthreads();

    for (int e = tid; e < Ee; e += 256) {
        float acc = 0.f;
        #pragma unroll
        for (int s = 0; s < Ss; s++)
            acc += wf[s] * x2[(size_t)(n * Ss + s) * Ee + e];
        g_pooled[(size_t)n * Ee + e] = acc;
    }
}

// ---------------- LSTM: 2 batches/block, fp16 weight streaming, L-step early exit ----------------
#define LCH2 64
#define LNCH2 4                        // 64,64,64,8
#define LBUF2 (LCH2*HC*8)              // 102400 B
#define LSTM_SMEM2 (2*LBUF2)           // 204800 B

__global__ void __launch_bounds__(512, 1)
lstm_kernel(const int* __restrict__ seq_lens)
{
    extern __shared__ __align__(16) char lsm[];
    __shared__ float h_s[2][HC];
    __shared__ float c_s[2][HC];
    const int dir = blockIdx.x & 1;
    const int pair = blockIdx.x >> 1;          // 0..15
    const uint2* __restrict__ wp = dir ? g_wpkh_b : g_wpkh_f;
    const int u = threadIdx.x;                 // 0..511
    const int grp = u >> 8;                    // batch within pair
    const int un = u & 255;                    // unit index
    const int b = pair * 2 + grp;
    const uint32_t sb0 = smem_to_u32(lsm);
    if (un < HC) { h_s[grp][un] = 0.f; c_s[grp][un] = 0.f; }
    __syncthreads();
    const int L = seq_lens[b];
    const int L0 = seq_lens[pair * 2];
    const int L1 = seq_lens[pair * 2 + 1];
    const int Lmax = (L0 > L1) ? L0 : L1;

    for (int t = 0; t < Lmax; t++) {
        const bool act = (t < L) && (un < HC);
        const int pos = dir ? (L - 1 - t) : t;
        float a0 = 0.f, a1 = 0.f, a2 = 0.f, a3 = 0.f;
        if (act) {
            const float* xr = g_xg + (size_t)(b * Tt + pos) * 1600 + dir * 800;
            a0 = xr[un]; a1 = xr[HC + un]; a2 = xr[2 * HC + un]; a3 = xr[3 * HC + un];
        }
        // chunk 0 -> buf 0 (6400 16B units)
        for (int i = u; i < 6400; i += 512)
            cp_async16(sb0 + (uint32_t)i * 16, wp + 2 * i);
        CP_COMMIT();

        for (int c = 0; c < LNCH2; c++) {
            const int k0 = c * LCH2;
            const int kcnt = (c < 3) ? LCH2 : (HC - 3 * LCH2);
            if (c + 1 < LNCH2) {
                const int ncnt = (c + 1 < 3) ? LCH2 : (HC - 3 * LCH2);
                const int units = ncnt * 100;
                const uint2* src = wp + (size_t)(c + 1) * LCH2 * HC;
                const uint32_t dstb = sb0 + ((c + 1) & 1) * LBUF2;
                for (int i = u; i < units; i += 512)
                    cp_async16(dstb + (uint32_t)i * 16, src + 2 * i);
                CP_COMMIT();
                CP_WAIT(1);
            } else {
                CP_WAIT(0);
            }
            __syncthreads();
            if (act) {
                const uint2* wb = reinterpret_cast<const uint2*>(lsm + (c & 1) * LBUF2);
                #pragma unroll 8
                for (int kk = 0; kk < kcnt; kk++) {
                    float hk = h_s[grp][k0 + kk];
                    uint2 w = wb[kk * HC + un];
                    float2 f0 = __half22float2(*reinterpret_cast<__half2*>(&w.x));
                    float2 f1 = __half22float2(*reinterpret_cast<__half2*>(&w.y));
                    a0 = fmaf(f0.x, hk, a0);
                    a1 = fmaf(f0.y, hk, a1);
                    a2 = fmaf(f1.x, hk, a2);
                    a3 = fmaf(f1.y, hk, a3);
                }
            }
            __syncthreads();
        }
        if (act) {
            float ig = 1.f / (1.f + expf(-a0));
            float fg = 1.f / (1.f + expf(-a1));
            float gg = tanhf(a2);
            float og = 1.f / (1.f + expf(-a3));
            float cc = fg * c_s[grp][un] + ig * gg;
            float hh = og * tanhf(cc);
            c_s[grp][un] = cc; h_s[grp][un] = hh;
            g_h[(size_t)(b * Tt + pos) * Hh + dir * HC + un] = hh;
        }
        __syncthreads();
    }
}

// ---------------- causal attention (prefix softmax-sum) ----------------
__global__ void __launch_bounds__(416)
causal_attn_kernel(const float* __restrict__ Wattn)
{
    __shared__ float ex[Tt];
    __shared__ float rz[Tt];
    int b = blockIdx.x;
    int tid = threadIdx.x;
    int warp = tid >> 5, lane = tid & 31;
    int nw = blockDim.x >> 5;

    for (int s = warp; s < Tt; s += nw) {
        const float* hr = g_h + (size_t)(b * Tt + s) * Hh;
        float d = 0.f;
        for (int j = lane; j < Hh; j += 32) d += hr[j] * Wattn[j];
        #pragma unroll
        for (int o = 16; o; o >>= 1) d += __shfl_down_sync(0xffffffffu, d, o);
        if (lane == 0) ex[s] = d;
    }
    __syncthreads();
    if (tid == 0) {
        float mx = -1e30f;
        for (int s = 0; s < Tt; s++) mx = fmaxf(mx, ex[s]);
        float z = 0.f;
        for (int s = 0; s < Tt; s++) {
            float e = expf(ex[s] - mx);
            z += e;
            ex[s] = e;
            rz[s] = 1.f / z;
        }
    }
    __syncthreads();

    if (tid < Hh) {
        int e = tid;
        float acc = 0.f;
        for (int t = 0; t < Tt; t++) {
            acc += ex[t] * g_h[(size_t)(b * Tt + t) * Hh + e];
            g_cat[(size_t)(b * Tt + t) * (2 * Hh) + e] = acc * rz[t];
        }
    }
}

// ---------------- launch ----------------
static inline void gemm2(cudaStream_t st, const __nv_bfloat16* Ah, const __nv_bfloat16* Al,
                         const __nv_bfloat16* Wh, const __nv_bfloat16* Wl,
                         const float* bias, float* C, __half* Ch, const int* mlens,
                         int M, int N, int Kp, int NC, int ldc)
{
    dim3 grid((N + 127) / 128, M / 128);
    tc_gemm2<<<grid, 256, GEMM_SMEM, st>>>(Ah, Al, Wh, Wl, bias, C, Ch, mlens, N, Kp, NC, ldc);
}

extern "C" void kernel_launch(void* const* d_in, const int* in_sizes, int n_in,
                              void* d_out, int out_size)
{
    const float* x1       = (const float*)d_in[0];
    const float* x2       = (const float*)d_in[1];
    const int*   seq_lens = (const int*)d_in[3];
    const float* w_ih_f   = (const float*)d_in[4];
    const float* w_hh_f   = (const float*)d_in[5];
    const float* b_ih_f   = (const float*)d_in[6];
    const float* b_hh_f   = (const float*)d_in[7];
    const float* w_ih_b   = (const float*)d_in[8];
    const float* w_hh_b   = (const float*)d_in[9];
    const float* b_ih_b   = (const float*)d_in[10];
    const float* b_hh_b   = (const float*)d_in[11];
    const float* w_q      = (const float*)d_in[12];
    const float* b_q      = (const float*)d_in[13];
    const float* w_k      = (const float*)d_in[14];
    const float* b_k      = (const float*)d_in[15];
    const float* w_mlp_mha= (const float*)d_in[16];
    const float* b_mlp_mha= (const float*)d_in[17];
    const float* W_attn   = (const float*)d_in[18];
    const float* w_mlp    = (const float*)d_in[20];
    const float* b_mlp    = (const float*)d_in[21];
    float* out = (float*)d_out;

    float *p_xg, *p_pooled, *p_cat, *p_bqk, *p_bs;
    __half* p_qkh;
    cudaGetSymbolAddress((void**)&p_qkh, g_qkh);
    cudaGetSymbolAddress((void**)&p_xg, g_xg);
    cudaGetSymbolAddress((void**)&p_pooled, g_pooled);
    cudaGetSymbolAddress((void**)&p_cat, g_cat);
    cudaGetSymbolAddress((void**)&p_bqk, g_bqk);
    cudaGetSymbolAddress((void**)&p_bs, g_bsum_cat);

    __nv_bfloat16 *x2h, *x2l, *x1h, *x1l, *plh, *pll, *cth, *ctl;
    __nv_bfloat16 *wqkh, *wqkl, *wihh, *wihl, *wmhah, *wmhal, *wmlph, *wmlpl;
    cudaGetSymbolAddress((void**)&x2h, g_x2h);   cudaGetSymbolAddress((void**)&x2l, g_x2l);
    cudaGetSymbolAddress((void**)&x1h, g_x1h);   cudaGetSymbolAddress((void**)&x1l, g_x1l);
    cudaGetSymbolAddress((void**)&plh, g_plh);   cudaGetSymbolAddress((void**)&pll, g_pll);
    cudaGetSymbolAddress((void**)&cth, g_cth);   cudaGetSymbolAddress((void**)&ctl, g_ctl);
    cudaGetSymbolAddress((void**)&wqkh, g_wqkh); cudaGetSymbolAddress((void**)&wqkl, g_wqkl);
    cudaGetSymbolAddress((void**)&wihh, g_wihh); cudaGetSymbolAddress((void**)&wihl, g_wihl);
    cudaGetSymbolAddress((void**)&wmhah, g_wmhah); cudaGetSymbolAddress((void**)&wmhal, g_wmhal);
    cudaGetSymbolAddress((void**)&wmlph, g_wmlph); cudaGetSymbolAddress((void**)&wmlpl, g_wmlpl);

    cudaFuncSetAttribute(tc_gemm2, cudaFuncAttributeMaxDynamicSharedMemorySize, GEMM_SMEM);
    cudaFuncSetAttribute(lstm_kernel, cudaFuncAttributeMaxDynamicSharedMemorySize, LSTM_SMEM2);
    size_t pool_smem = (size_t)(2 * Ss * PEE + 2 * Ss) * sizeof(float);
    cudaFuncSetAttribute(pool_kernel, cudaFuncAttributeMaxDynamicSharedMemorySize, (int)pool_smem);

    // ---- stream fork ----
    cudaStream_t s1;
    cudaStreamCreateWithFlags(&s1, cudaStreamNonBlocking);
    cudaEvent_t evFork, evPrep, evPrep2, evJoin;
    cudaEventCreateWithFlags(&evFork, cudaEventDisableTiming);
    cudaEventCreateWithFlags(&evPrep, cudaEventDisableTiming);
    cudaEventCreateWithFlags(&evPrep2, cudaEventDisableTiming);
    cudaEventCreateWithFlags(&evJoin, cudaEventDisableTiming);

    cudaEventRecord(evFork, 0);
    cudaStreamWaitEvent(s1, evFork, 0);

    // -- s1: prep_qk -> prep_rest -> x1 split -> xg GEMM -> LSTM -> attention --
    prep_qk_kernel<<<128, 256, 0, s1>>>(w_q, b_q, w_k, b_k);
    cudaEventRecord(evPrep, s1);
    prep_rest_kernel<<<512, 256, 0, s1>>>(b_ih_f, b_hh_f, b_ih_b, b_hh_b, w_hh_f, w_hh_b,
                                          w_ih_f, w_ih_b, w_mlp_mha, w_mlp);
    cudaEventRecord(evPrep2, s1);
    split_kernel<<<512, 256, 0, s1>>>(x1, x1h, x1l, NBT, Ee, KP1);
    gemm2(s1, x1h, x1l, wihh, wihl, p_bs, p_xg, nullptr, nullptr, NBT, 1600, KP1, 13, 1600);
    lstm_kernel<<<Bb, 512, LSTM_SMEM2, s1>>>(seq_lens);
    causal_attn_kernel<<<Bb, 416, 0, s1>>>(W_attn);
    cudaEventRecord(evJoin, s1);

    // -- s0: x2 split -> q|k GEMM (fp16 out) -> pool -> mha GEMM --
    split_kernel<<<8192, 256>>>(x2, x2h, x2l, NTOK, Ee, KP1);
    cudaStreamWaitEvent(0, evPrep, 0);
    gemm2(0, x2h, x2l, wqkh, wqkl, p_bqk, nullptr, p_qkh, nullptr, NTOK, 800, KP1, 13, 800);
    pool_kernel<<<NBT, 256, pool_smem>>>(x2);
    split_kernel<<<512, 256>>>(p_pooled, plh, pll, NBT, Ee, KP1);
    cudaStreamWaitEvent(0, evPrep2, 0);
    gemm2(0, plh, pll, wmhah, wmhal, b_mlp_mha, p_cat + Hh, nullptr, nullptr, NBT, Hh, KP1, 13, 2 * Hh);

    // -- join + epilogue (mask fused into out GEMM) --
    cudaStreamWaitEvent(0, evJoin, 0);
    split_kernel<<<1024, 256>>>(p_cat, cth, ctl, NBT, 800, 800);
    gemm2(0, cth, ctl, wmlph, wmlpl, b_mlp, out, nullptr, seq_lens, NBT, Ee, 800, 25, Ee);
}

// round 14
// speedup vs baseline: 1.1913x; 1.1913x over previous
#include <cuda_runtime.h>
#include <cuda_bf16.h>
#include <cuda_fp16.h>
#include <math.h>
#include <stdint.h>

// ---------------- problem constants ----------------
#define Bb 32
#define Tt 256
#define Ss 16
#define Ee 400
#define Hh 400
#define HC 200
#define NHd 20
#define DHd 20
#define NTOK (Bb*Tt*Ss)   // 131072
#define NBT  (Bb*Tt)      // 8192
#define KP1 416           // padded K for K=400 (13 chunks of 32)

// ---------------- scratch ----------------
__device__ __half g_qkh[(size_t)NTOK*800];   // fp16 q|k
__device__ float g_xg[(size_t)NBT*1600];
__device__ float g_pooled[(size_t)NBT*Ee];
__device__ float g_h[(size_t)NBT*Hh];        // zero-init; rows t>=L stay 0
__device__ float g_cat[(size_t)NBT*2*Hh];
__device__ uint2 g_wpkh_f[HC*HC];            // fp16 packed w_hh
__device__ uint2 g_wpkh_b[HC*HC];
__device__ float g_bqk[800];
__device__ float g_bsum_cat[1600];

// ---------------- bf16 hi/lo planes (zero-init => padding stays 0) ----------------
__device__ __nv_bfloat16 g_x2h[(size_t)NTOK*KP1];
__device__ __nv_bfloat16 g_x2l[(size_t)NTOK*KP1];
__device__ __nv_bfloat16 g_x1h[(size_t)NBT*KP1];
__device__ __nv_bfloat16 g_x1l[(size_t)NBT*KP1];
__device__ __nv_bfloat16 g_plh[(size_t)NBT*KP1];
__device__ __nv_bfloat16 g_pll[(size_t)NBT*KP1];
__device__ __nv_bfloat16 g_cth[(size_t)NBT*800];
__device__ __nv_bfloat16 g_ctl[(size_t)NBT*800];
__device__ __nv_bfloat16 g_wqkh[896*KP1];
__device__ __nv_bfloat16 g_wqkl[896*KP1];
__device__ __nv_bfloat16 g_wihh[1664*KP1];
__device__ __nv_bfloat16 g_wihl[1664*KP1];
__device__ __nv_bfloat16 g_wmhah[512*KP1];
__device__ __nv_bfloat16 g_wmhal[512*KP1];
__device__ __nv_bfloat16 g_wmlph[512*800];
__device__ __nv_bfloat16 g_wmlpl[512*800];

// =================== common helpers ===================
__device__ __forceinline__ uint32_t smem_to_u32(const void* p) {
    uint32_t a;
    asm("{ .reg .u64 t; cvta.to.shared.u64 t, %1; cvt.u32.u64 %0, t; }" : "=r"(a) : "l"(p));
    return a;
}
__device__ __forceinline__ void cp_async16(uint32_t saddr, const void* gaddr) {
    asm volatile("cp.async.cg.shared.global [%0], [%1], 16;" :: "r"(saddr), "l"(gaddr));
}
#define CP_COMMIT() asm volatile("cp.async.commit_group;" ::: "memory")
#define CP_WAIT(n)  asm volatile("cp.async.wait_group %0;" :: "n"(n) : "memory")

__device__ __forceinline__ void split4_store(float4 v, __nv_bfloat16* hp, __nv_bfloat16* lp) {
    __nv_bfloat16 h0 = __float2bfloat16(v.x);
    __nv_bfloat16 h1 = __float2bfloat16(v.y);
    __nv_bfloat16 h2 = __float2bfloat16(v.z);
    __nv_bfloat16 h3 = __float2bfloat16(v.w);
    __nv_bfloat16 l0 = __float2bfloat16(v.x - __bfloat162float(h0));
    __nv_bfloat16 l1 = __float2bfloat16(v.y - __bfloat162float(h1));
    __nv_bfloat16 l2 = __float2bfloat16(v.z - __bfloat162float(h2));
    __nv_bfloat16 l3 = __float2bfloat16(v.w - __bfloat162float(h3));
    uint2 hv, lv;
    hv.x = (uint32_t)__bfloat16_as_ushort(h0) | ((uint32_t)__bfloat16_as_ushort(h1) << 16);
    hv.y = (uint32_t)__bfloat16_as_ushort(h2) | ((uint32_t)__bfloat16_as_ushort(h3) << 16);
    lv.x = (uint32_t)__bfloat16_as_ushort(l0) | ((uint32_t)__bfloat16_as_ushort(l1) << 16);
    lv.y = (uint32_t)__bfloat16_as_ushort(l2) | ((uint32_t)__bfloat16_as_ushort(l3) << 16);
    *reinterpret_cast<uint2*>(hp) = hv;
    *reinterpret_cast<uint2*>(lp) = lv;
}

// =================== split: fp32 -> bf16 hi/lo planes ===================
__global__ void split_kernel(const float* __restrict__ src, __nv_bfloat16* __restrict__ dh,
                             __nv_bfloat16* __restrict__ dl, int M, int K, int Kp)
{
    const int kq = K >> 2;
    const int nv = M * kq;
    for (int i = blockIdx.x * blockDim.x + threadIdx.x; i < nv; i += gridDim.x * blockDim.x) {
        int row = i / kq;
        int c4 = (i - row * kq) * 4;
        float4 v = reinterpret_cast<const float4*>(src)[i];
        size_t off = (size_t)row * Kp + c4;
        split4_store(v, dh + off, dl + off);
    }
}

// =================== prep_qk: ONLY what the q|k GEMM needs ===================
__global__ void prep_qk_kernel(const float* __restrict__ w_q, const float* __restrict__ b_q,
                               const float* __restrict__ w_k, const float* __restrict__ b_k)
{
    const int gt = blockIdx.x * blockDim.x + threadIdx.x;
    const int gs = gridDim.x * blockDim.x;
    if (gt < 800) g_bqk[gt] = (gt < 400) ? b_q[gt] : b_k[gt - 400];
    for (int idx = gt; idx < 800 * 100; idx += gs) {
        int row = idx / 100, q4 = (idx - row * 100) * 4;
        const float* src = (row < 400) ? (w_q + (size_t)row * 400) : (w_k + (size_t)(row - 400) * 400);
        float4 v = *reinterpret_cast<const float4*>(src + q4);
        size_t off = (size_t)row * KP1 + q4;
        split4_store(v, g_wqkh + off, g_wqkl + off);
    }
}

// =================== prep_rest: biases + fp16 packed w_hh + other weight planes ===================
__global__ void prep_rest_kernel(const float* __restrict__ b_ih_f, const float* __restrict__ b_hh_f,
                                 const float* __restrict__ b_ih_b, const float* __restrict__ b_hh_b,
                                 const float* __restrict__ w_hh_f, const float* __restrict__ w_hh_b,
                                 const float* __restrict__ w_ih_f, const float* __restrict__ w_ih_b,
                                 const float* __restrict__ w_mlp_mha, const float* __restrict__ w_mlp)
{
    const int gt = blockIdx.x * blockDim.x + threadIdx.x;
    const int gs = gridDim.x * blockDim.x;

    if (gt < 1600) g_bsum_cat[gt] = (gt < 800) ? (b_ih_f[gt] + b_hh_f[gt])
                                               : (b_ih_b[gt - 800] + b_hh_b[gt - 800]);

    for (int idx = gt; idx < 1600 * 100; idx += gs) {
        int row = idx / 100, q4 = (idx - row * 100) * 4;
        const float* src = (row < 800) ? (w_ih_f + (size_t)row * 400) : (w_ih_b + (size_t)(row - 800) * 400);
        float4 v = *reinterpret_cast<const float4*>(src + q4);
        size_t off = (size_t)row * KP1 + q4;
        split4_store(v, g_wihh + off, g_wihl + off);
    }
    for (int idx = gt; idx < 400 * 100; idx += gs) {
        int row = idx / 100, q4 = (idx - row * 100) * 4;
        float4 v = *reinterpret_cast<const float4*>(w_mlp_mha + (size_t)row * 400 + q4);
        size_t off = (size_t)row * KP1 + q4;
        split4_store(v, g_wmhah + off, g_wmhal + off);
    }
    for (int idx = gt; idx < 400 * 200; idx += gs) {
        int row = idx / 200, q4 = (idx - row * 200) * 4;
        float4 v = *reinterpret_cast<const float4*>(w_mlp + (size_t)row * 800 + q4);
        size_t off = (size_t)row * 800 + q4;
        split4_store(v, g_wmlph + off, g_wmlpl + off);
    }
    for (int idx = gt; idx < HC * HC; idx += gs) {
        int k = idx / HC, u = idx % HC;
        {
            __half2 p0 = __floats2half2_rn(w_hh_f[(size_t)u * HC + k],          w_hh_f[(size_t)(HC + u) * HC + k]);
            __half2 p1 = __floats2half2_rn(w_hh_f[(size_t)(2*HC + u) * HC + k], w_hh_f[(size_t)(3*HC + u) * HC + k]);
            uint2 w;
            w.x = *reinterpret_cast<uint32_t*>(&p0);
            w.y = *reinterpret_cast<uint32_t*>(&p1);
            g_wpkh_f[idx] = w;
        }
        {
            __half2 p0 = __floats2half2_rn(w_hh_b[(size_t)u * HC + k],          w_hh_b[(size_t)(HC + u) * HC + k]);
            __half2 p1 = __floats2half2_rn(w_hh_b[(size_t)(2*HC + u) * HC + k], w_hh_b[(size_t)(3*HC + u) * HC + k]);
            uint2 w;
            w.x = *reinterpret_cast<uint32_t*>(&p0);
            w.y = *reinterpret_cast<uint32_t*>(&p1);
            g_wpkh_b[idx] = w;
        }
    }
}

// =================== bf16x3 mma.sync GEMM, pre-split operands, cp.async ===================
#define BKC 32
#define LDK 40
#define TILE_ELE (128*LDK)
#define TILE_B   (TILE_ELE*2)
#define STAGE_BYTES (4*TILE_B)
#define GEMM_SMEM (2*STAGE_BYTES + 512)
#define OFFB_AHI 0
#define OFFB_ALO TILE_B
#define OFFB_WHI (2*TILE_B)
#define OFFB_WLO (3*TILE_B)

#define MMA16816(d, a, b) \
    asm volatile("mma.sync.aligned.m16n8k16.row.col.f32.bf16.bf16.f32 " \
        "{%0,%1,%2,%3}, {%4,%5,%6,%7}, {%8,%9}, {%0,%1,%2,%3};" \
        : "+f"((d)[0]), "+f"((d)[1]), "+f"((d)[2]), "+f"((d)[3]) \
        : "r"((a)[0]), "r"((a)[1]), "r"((a)[2]), "r"((a)[3]), "r"((b)[0]), "r"((b)[1]))

#define LDSM4(r0, r1, r2, r3, addr) \
    asm volatile("ldmatrix.sync.aligned.m8n8.x4.shared.b16 {%0,%1,%2,%3}, [%4];" \
        : "=r"(r0), "=r"(r1), "=r"(r2), "=r"(r3) : "r"(addr))

__global__ void __launch_bounds__(256, 2)
tc_gemm2(const __nv_bfloat16* __restrict__ Ahi, const __nv_bfloat16* __restrict__ Alo,
         const __nv_bfloat16* __restrict__ Whi, const __nv_bfloat16* __restrict__ Wlo,
         const float* __restrict__ bias, float* __restrict__ C, __half* __restrict__ Ch,
         const int* __restrict__ mlens,
         int N, int Kp, int NC, int ldc)
{
    extern __shared__ __align__(1024) char smem[];
    const uint32_t sbu = smem_to_u32(smem);
    float* bsm = reinterpret_cast<float*>(smem + 2 * STAGE_BYTES);

    const int tid = threadIdx.x;
    const int lane = tid & 31, wid = tid >> 5;
    const int wm = wid & 3, wn = wid >> 2;
    const int m0 = blockIdx.y * 128;
    const int n0 = blockIdx.x * 128;

    const int rem = (N - n0) - wn * 64;
    const int ntmax = (rem >= 64) ? 8 : ((rem <= 0) ? 0 : ((rem + 7) >> 3));
    const int npair = (ntmax + 1) >> 1;

    const int crow = tid >> 2;
    const int cq = (tid & 3) * 8;
    const __nv_bfloat16* sAh0 = Ahi + (size_t)(m0 + crow) * Kp + cq;
    const __nv_bfloat16* sAh1 = Ahi + (size_t)(m0 + crow + 64) * Kp + cq;
    const __nv_bfloat16* sAl0 = Alo + (size_t)(m0 + crow) * Kp + cq;
    const __nv_bfloat16* sAl1 = Alo + (size_t)(m0 + crow + 64) * Kp + cq;
    const __nv_bfloat16* sWh0 = Whi + (size_t)(n0 + crow) * Kp + cq;
    const __nv_bfloat16* sWh1 = Whi + (size_t)(n0 + crow + 64) * Kp + cq;
    const __nv_bfloat16* sWl0 = Wlo + (size_t)(n0 + crow) * Kp + cq;
    const __nv_bfloat16* sWl1 = Wlo + (size_t)(n0 + crow + 64) * Kp + cq;
    const uint32_t doff0 = (uint32_t)((crow * LDK + cq) * 2);
    const uint32_t doff1 = (uint32_t)(((crow + 64) * LDK + cq) * 2);

    const int ro = lane & 15;
    const int khalf = (lane >> 4) << 3;
    const uint32_t aoff0 = (uint32_t)(((wm * 32 + ro) * LDK + khalf) * 2);
    const uint32_t aoff1 = aoff0 + 16 * LDK * 2;
    uint32_t boff[4];
    #pragma unroll
    for (int p = 0; p < 4; p++)
        boff[p] = (uint32_t)(((wn * 64 + p * 16 + ro) * LDK + khalf) * 2);

    if (tid < 128) bsm[tid] = (n0 + tid < N) ? bias[n0 + tid] : 0.f;

    float acc[2][8][4];
    #pragma unroll
    for (int i = 0; i < 2; i++)
        #pragma unroll
        for (int j = 0; j < 8; j++)
            #pragma unroll
            for (int q = 0; q < 4; q++) acc[i][j][q] = 0.f;

    #define ISSUE_CHUNK(cc, st) do { \
        const int _k0 = (cc) * BKC; \
        const uint32_t _db = sbu + (st) * STAGE_BYTES; \
        cp_async16(_db + OFFB_AHI + doff0, sAh0 + _k0); \
        cp_async16(_db + OFFB_AHI + doff1, sAh1 + _k0); \
        cp_async16(_db + OFFB_ALO + doff0, sAl0 + _k0); \
        cp_async16(_db + OFFB_ALO + doff1, sAl1 + _k0); \
        cp_async16(_db + OFFB_WHI + doff0, sWh0 + _k0); \
        cp_async16(_db + OFFB_WHI + doff1, sWh1 + _k0); \
        cp_async16(_db + OFFB_WLO + doff0, sWl0 + _k0); \
        cp_async16(_db + OFFB_WLO + doff1, sWl1 + _k0); \
    } while (0)

    ISSUE_CHUNK(0, 0);
    CP_COMMIT();

    for (int c = 0; c < NC; c++) {
        if (c + 1 < NC) {
            ISSUE_CHUNK(c + 1, (c + 1) & 1);
            CP_COMMIT();
            CP_WAIT(1);
        } else {
            CP_WAIT(0);
        }
        __syncthreads();

        if (npair > 0) {
            const uint32_t base = sbu + (c & 1) * STAGE_BYTES;
            #pragma unroll
            for (int ks = 0; ks < 2; ks++) {
                const uint32_t kb = base + ks * 32;
                uint32_t ah[2][4], al[2][4];
                LDSM4(ah[0][0], ah[0][1], ah[0][2], ah[0][3], kb + OFFB_AHI + aoff0);
                LDSM4(ah[1][0], ah[1][1], ah[1][2], ah[1][3], kb + OFFB_AHI + aoff1);
                LDSM4(al[0][0], al[0][1], al[0][2], al[0][3], kb + OFFB_ALO + aoff0);
                LDSM4(al[1][0], al[1][1], al[1][2], al[1][3], kb + OFFB_ALO + aoff1);
                #pragma unroll
                for (int p = 0; p < 4; p++) {
                    if (p < npair) {
                        uint32_t u0, u1, u2, u3;
                        LDSM4(u0, u1, u2, u3, kb + OFFB_WHI + boff[p]);
                        uint32_t f0[2] = {u0, u2};
                        uint32_t f1[2] = {u1, u3};
                        MMA16816(acc[0][2*p],   ah[0], f0);
                        MMA16816(acc[1][2*p],   ah[1], f0);
                        MMA16816(acc[0][2*p+1], ah[0], f1);
                        MMA16816(acc[1][2*p+1], ah[1], f1);
                        MMA16816(acc[0][2*p],   al[0], f0);
                        MMA16816(acc[1][2*p],   al[1], f0);
                        MMA16816(acc[0][2*p+1], al[0], f1);
                        MMA16816(acc[1][2*p+1], al[1], f1);
                        LDSM4(u0, u1, u2, u3, kb + OFFB_WLO + boff[p]);
                        uint32_t g0[2] = {u0, u2};
                        uint32_t g1[2] = {u1, u3};
                        MMA16816(acc[0][2*p],   ah[0], g0);
                        MMA16816(acc[1][2*p],   ah[1], g0);
                        MMA16816(acc[0][2*p+1], ah[0], g1);
                        MMA16816(acc[1][2*p+1], ah[1], g1);
                    }
                }
            }
        }
        __syncthreads();
    }

    const int g = lane >> 2, t = lane & 3;
    #pragma unroll
    for (int mt = 0; mt < 2; mt++) {
        int row_a = m0 + wm * 32 + mt * 16 + g;
        int row_b = row_a + 8;
        if (Ch) {
            __half* ca = Ch + (size_t)row_a * ldc;
            __half* cb = Ch + (size_t)row_b * ldc;
            #pragma unroll
            for (int nt = 0; nt < 8; nt++) {
                int lc = wn * 64 + nt * 8 + 2 * t;
                int n = n0 + lc;
                if (n < N) {
                    float b0 = bsm[lc], b1 = bsm[lc + 1];
                    __half2 v0 = __floats2half2_rn(acc[mt][nt][0] + b0, acc[mt][nt][1] + b1);
                    __half2 v1 = __floats2half2_rn(acc[mt][nt][2] + b0, acc[mt][nt][3] + b1);
                    *reinterpret_cast<__half2*>(ca + n) = v0;
                    *reinterpret_cast<__half2*>(cb + n) = v1;
                }
            }
        } else {
            float va = 1.f, vb = 1.f;
            if (mlens) {
                va = ((row_a & (Tt - 1)) < mlens[row_a >> 8]) ? 1.f : 0.f;
                vb = ((row_b & (Tt - 1)) < mlens[row_b >> 8]) ? 1.f : 0.f;
            }
            float* ca = C + (size_t)row_a * ldc;
            float* cb = C + (size_t)row_b * ldc;
            #pragma unroll
            for (int nt = 0; nt < 8; nt++) {
                int lc = wn * 64 + nt * 8 + 2 * t;
                int n = n0 + lc;
                if (n < N) {
                    float b0 = bsm[lc], b1 = bsm[lc + 1];
                    *reinterpret_cast<float2*>(ca + n) = make_float2((acc[mt][nt][0] + b0) * va, (acc[mt][nt][1] + b1) * va);
                    *reinterpret_cast<float2*>(cb + n) = make_float2((acc[mt][nt][2] + b0) * vb, (acc[mt][nt][3] + b1) * vb);
                }
            }
        }
    }
}

// ---------------- per-news MHA pooling (fp16 q|k input) — round-11 proven form ----------------
#define PEE 402
__global__ void __launch_bounds__(256)
pool_kernel(const float* __restrict__ x2)
{
    extern __shared__ float sm[];
    float* qs = sm;
    float* ks = sm + Ss * PEE;
    float* msm = sm + 2 * Ss * PEE;
    float* wf  = msm + Ss;
    const int n = blockIdx.x;
    const int tid = threadIdx.x;
    const int lane = tid & 31, warp = tid >> 5;

    for (int i = tid; i < Ss * Ee; i += 256) {
        int row = i / Ee, col = i % Ee;
        const __half* src = g_qkh + (size_t)(n * Ss + row) * 800;
        qs[row * PEE + col] = __half2float(src[col]);
        ks[row * PEE + col] = __half2float(src[400 + col]);
    }
    __syncthreads();

    const float scale = rsqrtf((float)DHd);
    const int half = lane >> 4;
    const int kl = lane & 15;

    #pragma unroll
    for (int rep = 0; rep < 2; rep++) {
        const int qi = warp + 8 * rep;
        float accw = 0.f;
        const float* kp_base = ks + kl * PEE;
        const float* qp_base = qs + qi * PEE;
        #pragma unroll
        for (int hh = 0; hh < 10; hh++) {
            int h = 2 * hh + half;
            const float* qp = qp_base + h * DHd;
            const float* kp = kp_base + h * DHd;
            float s = 0.f;
            #pragma unroll
            for (int d = 0; d < DHd; d++) s = fmaf(qp[d], kp[d], s);
            s *= scale;
            float mx = s;
            #pragma unroll
            for (int o = 8; o; o >>= 1) mx = fmaxf(mx, __shfl_xor_sync(0xffffffffu, mx, o));
            float e = expf(s - mx);
            float sum = e;
            #pragma unroll
            for (int o = 8; o; o >>= 1) sum += __shfl_xor_sync(0xffffffffu, sum, o);
            accw += e / (sum * (float)NHd);
        }
        accw += __shfl_xor_sync(0xffffffffu, accw, 16);
        float tot = accw;
        #pragma unroll
        for (int o = 8; o; o >>= 1) tot += __shfl_xor_sync(0xffffffffu, tot, o);
        if (lane == 0) msm[qi] = tot * (1.f / (float)Ss);
    }
    __syncthreads();

    if (warp == 0) {
        float v = (lane < Ss) ? msm[lane] : -1e30f;
        float mx = v;
        #pragma unroll
        for (int o = 8; o; o >>= 1) mx = fmaxf(mx, __shfl_xor_sync(0xffffffffu, mx, o));
        mx = fmaxf(mx, __shfl_xor_sync(0xffffffffu, mx, 16));
        float e = (lane < Ss) ? expf(v - mx) : 0.f;
        float z = e;
        #pragma unroll
        for (int o = 8; o; o >>= 1) z += __shfl_xor_sync(0xffffffffu, z, o);
        z += __shfl_xor_sync(0xffffffffu, z, 16);
        if (lane < Ss) wf[lane] = e / z;
    }
    __syncthreads();

    for (int e = tid; e < Ee; e += 256) {
        float acc = 0.f;
        #pragma unroll
        for (int s = 0; s < Ss; s++)
            acc += wf[s] * x2[(size_t)(n * Ss + s) * Ee + e];
        g_pooled[(size_t)n * Ee + e] = acc;
    }
}

// ---------------- LSTM: round-11 proven form (grid 64, 256 thr, fp16 streaming) ----------------
#define LCH2 64
#define LNCH2 4                        // 64,64,64,8
#define LBUF2 (LCH2*HC*8)              // 102400 B
#define LSTM_SMEM2 (2*LBUF2)           // 204800 B

__global__ void __launch_bounds__(256, 1)
lstm_kernel(const int* __restrict__ seq_lens)
{
    extern __shared__ __align__(16) char lsm[];
    __shared__ float h_s[HC];
    __shared__ float c_s[HC];
    const int dir = blockIdx.x & 1;
    const int b = blockIdx.x >> 1;
    const uint2* __restrict__ wp = dir ? g_wpkh_b : g_wpkh_f;
    const int u = threadIdx.x;
    const uint32_t sb0 = smem_to_u32(lsm);
    if (u < HC) { h_s[u] = 0.f; c_s[u] = 0.f; }
    __syncthreads();
    const int L = seq_lens[b];

    for (int t = 0; t < L; t++) {
        const int pos = dir ? (L - 1 - t) : t;
        float a0 = 0.f, a1 = 0.f, a2 = 0.f, a3 = 0.f;
        if (u < HC) {
            const float* xr = g_xg + (size_t)(b * Tt + pos) * 1600 + dir * 800;
            a0 = xr[u]; a1 = xr[HC + u]; a2 = xr[2 * HC + u]; a3 = xr[3 * HC + u];
        }
        {
            #pragma unroll
            for (int r = 0; r < 25; r++) {
                int i = u + r * 256;
                cp_async16(sb0 + (uint32_t)i * 16, wp + 2 * i);
            }
            CP_COMMIT();
        }
        for (int c = 0; c < LNCH2; c++) {
            const int k0 = c * LCH2;
            const int kcnt = (c < 3) ? LCH2 : (HC - 3 * LCH2);
            if (c + 1 < LNCH2) {
                const int ncnt = (c + 1 < 3) ? LCH2 : (HC - 3 * LCH2);
                const int units = ncnt * 100;
                const uint2* src = wp + (size_t)(c + 1) * LCH2 * HC;
                const uint32_t dstb = sb0 + ((c + 1) & 1) * LBUF2;
                for (int i = u; i < units; i += 256)
                    cp_async16(dstb + (uint32_t)i * 16, src + 2 * i);
                CP_COMMIT();
                CP_WAIT(1);
            } else {
                CP_WAIT(0);
            }
            __syncthreads();
            if (u < HC) {
                const uint2* wb = reinterpret_cast<const uint2*>(lsm + (c & 1) * LBUF2);
                #pragma unroll 8
                for (int kk = 0; kk < kcnt; kk++) {
                    float hk = h_s[k0 + kk];
                    uint2 w = wb[kk * HC + u];
                    float2 f0 = __half22float2(*reinterpret_cast<__half2*>(&w.x));
                    float2 f1 = __half22float2(*reinterpret_cast<__half2*>(&w.y));
                    a0 = fmaf(f0.x, hk, a0);
                    a1 = fmaf(f0.y, hk, a1);
                    a2 = fmaf(f1.x, hk, a2);
                    a3 = fmaf(f1.y, hk, a3);
                }
            }
            __syncthreads();
        }
        if (u < HC) {
            float ig = 1.f / (1.f + expf(-a0));
            float fg = 1.f / (1.f + expf(-a1));
            float gg = tanhf(a2);
            float og = 1.f / (1.f + expf(-a3));
            float cc = fg * c_s[u] + ig * gg;
            float hh = og * tanhf(cc);
            c_s[u] = cc; h_s[u] = hh;
            g_h[(size_t)(b * Tt + pos) * Hh + dir * HC + u] = hh;
        }
        __syncthreads();
    }
}

// ---------------- causal attention (prefix softmax-sum) ----------------
__global__ void __launch_bounds__(416)
causal_attn_kernel(const float* __restrict__ Wattn)
{
    __shared__ float ex[Tt];
    __shared__ float rz[Tt];
    int b = blockIdx.x;
    int tid = threadIdx.x;
    int warp = tid >> 5, lane = tid & 31;
    int nw = blockDim.x >> 5;

    for (int s = warp; s < Tt; s += nw) {
        const float* hr = g_h + (size_t)(b * Tt + s) * Hh;
        float d = 0.f;
        for (int j = lane; j < Hh; j += 32) d += hr[j] * Wattn[j];
        #pragma unroll
        for (int o = 16; o; o >>= 1) d += __shfl_down_sync(0xffffffffu, d, o);
        if (lane == 0) ex[s] = d;
    }
    __syncthreads();
    if (tid == 0) {
        float mx = -1e30f;
        for (int s = 0; s < Tt; s++) mx = fmaxf(mx, ex[s]);
        float z = 0.f;
        for (int s = 0; s < Tt; s++) {
            float e = expf(ex[s] - mx);
            z += e;
            ex[s] = e;
            rz[s] = 1.f / z;
        }
    }
    __syncthreads();

    if (tid < Hh) {
        int e = tid;
        float acc = 0.f;
        for (int t = 0; t < Tt; t++) {
            acc += ex[t] * g_h[(size_t)(b * Tt + t) * Hh + e];
            g_cat[(size_t)(b * Tt + t) * (2 * Hh) + e] = acc * rz[t];
        }
    }
}

// ---------------- launch ----------------
static inline void gemm2(cudaStream_t st, const __nv_bfloat16* Ah, const __nv_bfloat16* Al,
                         const __nv_bfloat16* Wh, const __nv_bfloat16* Wl,
                         const float* bias, float* C, __half* Ch, const int* mlens,
                         int M, int N, int Kp, int NC, int ldc)
{
    dim3 grid((N + 127) / 128, M / 128);
    tc_gemm2<<<grid, 256, GEMM_SMEM, st>>>(Ah, Al, Wh, Wl, bias, C, Ch, mlens, N, Kp, NC, ldc);
}

extern "C" void kernel_launch(void* const* d_in, const int* in_sizes, int n_in,
                              void* d_out, int out_size)
{
    const float* x1       = (const float*)d_in[0];
    const float* x2       = (const float*)d_in[1];
    const int*   seq_lens = (const int*)d_in[3];
    const float* w_ih_f   = (const float*)d_in[4];
    const float* w_hh_f   = (const float*)d_in[5];
    const float* b_ih_f   = (const float*)d_in[6];
    const float* b_hh_f   = (const float*)d_in[7];
    const float* w_ih_b   = (const float*)d_in[8];
    const float* w_hh_b   = (const float*)d_in[9];
    const float* b_ih_b   = (const float*)d_in[10];
    const float* b_hh_b   = (const float*)d_in[11];
    const float* w_q      = (const float*)d_in[12];
    const float* b_q      = (const float*)d_in[13];
    const float* w_k      = (const float*)d_in[14];
    const float* b_k      = (const float*)d_in[15];
    const float* w_mlp_mha= (const float*)d_in[16];
    const float* b_mlp_mha= (const float*)d_in[17];
    const float* W_attn   = (const float*)d_in[18];
    const float* w_mlp    = (const float*)d_in[20];
    const float* b_mlp    = (const float*)d_in[21];
    float* out = (float*)d_out;

    float *p_xg, *p_pooled, *p_cat, *p_bqk, *p_bs;
    __half* p_qkh;
    cudaGetSymbolAddress((void**)&p_qkh, g_qkh);
    cudaGetSymbolAddress((void**)&p_xg, g_xg);
    cudaGetSymbolAddress((void**)&p_pooled, g_pooled);
    cudaGetSymbolAddress((void**)&p_cat, g_cat);
    cudaGetSymbolAddress((void**)&p_bqk, g_bqk);
    cudaGetSymbolAddress((void**)&p_bs, g_bsum_cat);

    __nv_bfloat16 *x2h, *x2l, *x1h, *x1l, *plh, *pll, *cth, *ctl;
    __nv_bfloat16 *wqkh, *wqkl, *wihh, *wihl, *wmhah, *wmhal, *wmlph, *wmlpl;
    cudaGetSymbolAddress((void**)&x2h, g_x2h);   cudaGetSymbolAddress((void**)&x2l, g_x2l);
    cudaGetSymbolAddress((void**)&x1h, g_x1h);   cudaGetSymbolAddress((void**)&x1l, g_x1l);
    cudaGetSymbolAddress((void**)&plh, g_plh);   cudaGetSymbolAddress((void**)&pll, g_pll);
    cudaGetSymbolAddress((void**)&cth, g_cth);   cudaGetSymbolAddress((void**)&ctl, g_ctl);
    cudaGetSymbolAddress((void**)&wqkh, g_wqkh); cudaGetSymbolAddress((void**)&wqkl, g_wqkl);
    cudaGetSymbolAddress((void**)&wihh, g_wihh); cudaGetSymbolAddress((void**)&wihl, g_wihl);
    cudaGetSymbolAddress((void**)&wmhah, g_wmhah); cudaGetSymbolAddress((void**)&wmhal, g_wmhal);
    cudaGetSymbolAddress((void**)&wmlph, g_wmlph); cudaGetSymbolAddress((void**)&wmlpl, g_wmlpl);

    cudaFuncSetAttribute(tc_gemm2, cudaFuncAttributeMaxDynamicSharedMemorySize, GEMM_SMEM);
    cudaFuncSetAttribute(lstm_kernel, cudaFuncAttributeMaxDynamicSharedMemorySize, LSTM_SMEM2);
    size_t pool_smem = (size_t)(2 * Ss * PEE + 2 * Ss) * sizeof(float);
    cudaFuncSetAttribute(pool_kernel, cudaFuncAttributeMaxDynamicSharedMemorySize, (int)pool_smem);

    // ---- stream fork ----
    cudaStream_t s1;
    cudaStreamCreateWithFlags(&s1, cudaStreamNonBlocking);
    cudaEvent_t evFork, evPrep, evPrep2, evJoin;
    cudaEventCreateWithFlags(&evFork, cudaEventDisableTiming);
    cudaEventCreateWithFlags(&evPrep, cudaEventDisableTiming);
    cudaEventCreateWithFlags(&evPrep2, cudaEventDisableTiming);
    cudaEventCreateWithFlags(&evJoin, cudaEventDisableTiming);

    cudaEventRecord(evFork, 0);
    cudaStreamWaitEvent(s1, evFork, 0);

    // -- s1: prep_qk -> prep_rest -> x1 split -> xg GEMM -> LSTM -> attention --
    prep_qk_kernel<<<128, 256, 0, s1>>>(w_q, b_q, w_k, b_k);
    cudaEventRecord(evPrep, s1);
    prep_rest_kernel<<<512, 256, 0, s1>>>(b_ih_f, b_hh_f, b_ih_b, b_hh_b, w_hh_f, w_hh_b,
                                          w_ih_f, w_ih_b, w_mlp_mha, w_mlp);
    cudaEventRecord(evPrep2, s1);
    split_kernel<<<512, 256, 0, s1>>>(x1, x1h, x1l, NBT, Ee, KP1);
    gemm2(s1, x1h, x1l, wihh, wihl, p_bs, p_xg, nullptr, nullptr, NBT, 1600, KP1, 13, 1600);
    lstm_kernel<<<2 * Bb, 256, LSTM_SMEM2, s1>>>(seq_lens);
    causal_attn_kernel<<<Bb, 416, 0, s1>>>(W_attn);
    cudaEventRecord(evJoin, s1);

    // -- s0: x2 split -> q|k GEMM (fp16 out) -> pool -> mha GEMM --
    split_kernel<<<8192, 256>>>(x2, x2h, x2l, NTOK, Ee, KP1);
    cudaStreamWaitEvent(0, evPrep, 0);
    gemm2(0, x2h, x2l, wqkh, wqkl, p_bqk, nullptr, p_qkh, nullptr, NTOK, 800, KP1, 13, 800);
    pool_kernel<<<NBT, 256, pool_smem>>>(x2);
    split_kernel<<<512, 256>>>(p_pooled, plh, pll, NBT, Ee, KP1);
    cudaStreamWaitEvent(0, evPrep2, 0);
    gemm2(0, plh, pll, wmhah, wmhal, b_mlp_mha, p_cat + Hh, nullptr, nullptr, NBT, Hh, KP1, 13, 2 * Hh);

    // -- join + epilogue (mask fused into out GEMM) --
    cudaStreamWaitEvent(0, evJoin, 0);
    split_kernel<<<1024, 256>>>(p_cat, cth, ctl, NBT, 800, 800);
    gemm2(0, cth, ctl, wmlph, wmlpl, b_mlp, out, nullptr, seq_lens, NBT, Ee, 800, 25, Ee);
}

// round 15
// speedup vs baseline: 1.3171x; 1.1056x over previous
#include <cuda_runtime.h>
#include <cuda_bf16.h>
#include <cuda_fp16.h>
#include <math.h>
#include <stdint.h>

// ---------------- problem constants ----------------
#define Bb 32
#define Tt 256
#define Ss 16
#define Ee 400
#define Hh 400
#define HC 200
#define NHd 20
#define DHd 20
#define NTOK (Bb*Tt*Ss)   // 131072
#define NBT  (Bb*Tt)      // 8192
#define KP1 416           // padded K for K=400 (13 chunks of 32)

// ---------------- scratch ----------------
__device__ __half g_qkh[(size_t)NTOK*800];   // fp16 q|k
__device__ float g_xg[(size_t)NBT*1600];
__device__ float g_pooled[(size_t)NBT*Ee];
__device__ float g_h[(size_t)NBT*Hh];        // zero-init; rows t>=L stay 0
__device__ float g_cat[(size_t)NBT*2*Hh];
__device__ uint2 g_wpkh_f[HC*HC];            // fp16 packed w_hh
__device__ uint2 g_wpkh_b[HC*HC];
__device__ float g_bqk[800];
__device__ float g_bsum_cat[1600];

// ---------------- bf16 hi/lo planes (zero-init => padding stays 0) ----------------
__device__ __nv_bfloat16 g_x2h[(size_t)NTOK*KP1];
__device__ __nv_bfloat16 g_x2l[(size_t)NTOK*KP1];
__device__ __nv_bfloat16 g_x1h[(size_t)NBT*KP1];
__device__ __nv_bfloat16 g_x1l[(size_t)NBT*KP1];
__device__ __nv_bfloat16 g_plh[(size_t)NBT*KP1];
__device__ __nv_bfloat16 g_pll[(size_t)NBT*KP1];
__device__ __nv_bfloat16 g_cth[(size_t)NBT*800];
__device__ __nv_bfloat16 g_ctl[(size_t)NBT*800];
__device__ __nv_bfloat16 g_wqkh[896*KP1];
__device__ __nv_bfloat16 g_wqkl[896*KP1];
__device__ __nv_bfloat16 g_wihh[1664*KP1];
__device__ __nv_bfloat16 g_wihl[1664*KP1];
__device__ __nv_bfloat16 g_wmhah[512*KP1];
__device__ __nv_bfloat16 g_wmhal[512*KP1];
__device__ __nv_bfloat16 g_wmlph[512*800];
__device__ __nv_bfloat16 g_wmlpl[512*800];

// =================== common helpers ===================
__device__ __forceinline__ uint32_t smem_to_u32(const void* p) {
    uint32_t a;
    asm("{ .reg .u64 t; cvta.to.shared.u64 t, %1; cvt.u32.u64 %0, t; }" : "=r"(a) : "l"(p));
    return a;
}
__device__ __forceinline__ void cp_async16(uint32_t saddr, const void* gaddr) {
    asm volatile("cp.async.cg.shared.global [%0], [%1], 16;" :: "r"(saddr), "l"(gaddr));
}
#define CP_COMMIT() asm volatile("cp.async.commit_group;" ::: "memory")
#define CP_WAIT(n)  asm volatile("cp.async.wait_group %0;" :: "n"(n) : "memory")

__device__ __forceinline__ void split4_store(float4 v, __nv_bfloat16* hp, __nv_bfloat16* lp) {
    __nv_bfloat16 h0 = __float2bfloat16(v.x);
    __nv_bfloat16 h1 = __float2bfloat16(v.y);
    __nv_bfloat16 h2 = __float2bfloat16(v.z);
    __nv_bfloat16 h3 = __float2bfloat16(v.w);
    __nv_bfloat16 l0 = __float2bfloat16(v.x - __bfloat162float(h0));
    __nv_bfloat16 l1 = __float2bfloat16(v.y - __bfloat162float(h1));
    __nv_bfloat16 l2 = __float2bfloat16(v.z - __bfloat162float(h2));
    __nv_bfloat16 l3 = __float2bfloat16(v.w - __bfloat162float(h3));
    uint2 hv, lv;
    hv.x = (uint32_t)__bfloat16_as_ushort(h0) | ((uint32_t)__bfloat16_as_ushort(h1) << 16);
    hv.y = (uint32_t)__bfloat16_as_ushort(h2) | ((uint32_t)__bfloat16_as_ushort(h3) << 16);
    lv.x = (uint32_t)__bfloat16_as_ushort(l0) | ((uint32_t)__bfloat16_as_ushort(l1) << 16);
    lv.y = (uint32_t)__bfloat16_as_ushort(l2) | ((uint32_t)__bfloat16_as_ushort(l3) << 16);
    *reinterpret_cast<uint2*>(hp) = hv;
    *reinterpret_cast<uint2*>(lp) = lv;
}

// =================== split: fp32 -> bf16 hi/lo planes ===================
__global__ void split_kernel(const float* __restrict__ src, __nv_bfloat16* __restrict__ dh,
                             __nv_bfloat16* __restrict__ dl, int M, int K, int Kp)
{
    const int kq = K >> 2;
    const int nv = M * kq;
    for (int i = blockIdx.x * blockDim.x + threadIdx.x; i < nv; i += gridDim.x * blockDim.x) {
        int row = i / kq;
        int c4 = (i - row * kq) * 4;
        float4 v = reinterpret_cast<const float4*>(src)[i];
        size_t off = (size_t)row * Kp + c4;
        split4_store(v, dh + off, dl + off);
    }
}

// =================== prep: biases + fp16 packed w_hh + all weight bf16 planes ===================
__global__ void prep_kernel(const float* __restrict__ b_ih_f, const float* __restrict__ b_hh_f,
                            const float* __restrict__ b_ih_b, const float* __restrict__ b_hh_b,
                            const float* __restrict__ w_hh_f, const float* __restrict__ w_hh_b,
                            const float* __restrict__ w_ih_f, const float* __restrict__ w_ih_b,
                            const float* __restrict__ w_q,   const float* __restrict__ b_q,
                            const float* __restrict__ w_k,   const float* __restrict__ b_k,
                            const float* __restrict__ w_mlp_mha, const float* __restrict__ w_mlp)
{
    const int gt = blockIdx.x * blockDim.x + threadIdx.x;
    const int gs = gridDim.x * blockDim.x;

    if (gt < 800)  g_bqk[gt] = (gt < 400) ? b_q[gt] : b_k[gt - 400];
    if (gt < 1600) g_bsum_cat[gt] = (gt < 800) ? (b_ih_f[gt] + b_hh_f[gt])
                                               : (b_ih_b[gt - 800] + b_hh_b[gt - 800]);

    for (int idx = gt; idx < 800 * 100; idx += gs) {
        int row = idx / 100, q4 = (idx - row * 100) * 4;
        const float* src = (row < 400) ? (w_q + (size_t)row * 400) : (w_k + (size_t)(row - 400) * 400);
        float4 v = *reinterpret_cast<const float4*>(src + q4);
        size_t off = (size_t)row * KP1 + q4;
        split4_store(v, g_wqkh + off, g_wqkl + off);
    }
    for (int idx = gt; idx < 1600 * 100; idx += gs) {
        int row = idx / 100, q4 = (idx - row * 100) * 4;
        const float* src = (row < 800) ? (w_ih_f + (size_t)row * 400) : (w_ih_b + (size_t)(row - 800) * 400);
        float4 v = *reinterpret_cast<const float4*>(src + q4);
        size_t off = (size_t)row * KP1 + q4;
        split4_store(v, g_wihh + off, g_wihl + off);
    }
    for (int idx = gt; idx < 400 * 100; idx += gs) {
        int row = idx / 100, q4 = (idx - row * 100) * 4;
        float4 v = *reinterpret_cast<const float4*>(w_mlp_mha + (size_t)row * 400 + q4);
        size_t off = (size_t)row * KP1 + q4;
        split4_store(v, g_wmhah + off, g_wmhal + off);
    }
    for (int idx = gt; idx < 400 * 200; idx += gs) {
        int row = idx / 200, q4 = (idx - row * 200) * 4;
        float4 v = *reinterpret_cast<const float4*>(w_mlp + (size_t)row * 800 + q4);
        size_t off = (size_t)row * 800 + q4;
        split4_store(v, g_wmlph + off, g_wmlpl + off);
    }
    // fp16 packed w_hh for LSTM: (k,u) -> halves (i,f,g,o)
    for (int idx = gt; idx < HC * HC; idx += gs) {
        int k = idx / HC, u = idx % HC;
        {
            __half2 p0 = __floats2half2_rn(w_hh_f[(size_t)u * HC + k],        w_hh_f[(size_t)(HC + u) * HC + k]);
            __half2 p1 = __floats2half2_rn(w_hh_f[(size_t)(2*HC + u) * HC + k], w_hh_f[(size_t)(3*HC + u) * HC + k]);
            uint2 w;
            w.x = *reinterpret_cast<uint32_t*>(&p0);
            w.y = *reinterpret_cast<uint32_t*>(&p1);
            g_wpkh_f[idx] = w;
        }
        {
            __half2 p0 = __floats2half2_rn(w_hh_b[(size_t)u * HC + k],        w_hh_b[(size_t)(HC + u) * HC + k]);
            __half2 p1 = __floats2half2_rn(w_hh_b[(size_t)(2*HC + u) * HC + k], w_hh_b[(size_t)(3*HC + u) * HC + k]);
            uint2 w;
            w.x = *reinterpret_cast<uint32_t*>(&p0);
            w.y = *reinterpret_cast<uint32_t*>(&p1);
            g_wpkh_b[idx] = w;
        }
    }
}

// =================== bf16x3 mma.sync GEMM, pre-split operands, cp.async ===================
#define BKC 32
#define LDK 40
#define TILE_ELE (128*LDK)
#define TILE_B   (TILE_ELE*2)
#define STAGE_BYTES (4*TILE_B)
#define GEMM_SMEM (2*STAGE_BYTES + 512)
#define OFFB_AHI 0
#define OFFB_ALO TILE_B
#define OFFB_WHI (2*TILE_B)
#define OFFB_WLO (3*TILE_B)

#define MMA16816(d, a, b) \
    asm volatile("mma.sync.aligned.m16n8k16.row.col.f32.bf16.bf16.f32 " \
        "{%0,%1,%2,%3}, {%4,%5,%6,%7}, {%8,%9}, {%0,%1,%2,%3};" \
        : "+f"((d)[0]), "+f"((d)[1]), "+f"((d)[2]), "+f"((d)[3]) \
        : "r"((a)[0]), "r"((a)[1]), "r"((a)[2]), "r"((a)[3]), "r"((b)[0]), "r"((b)[1]))

#define LDSM4(r0, r1, r2, r3, addr) \
    asm volatile("ldmatrix.sync.aligned.m8n8.x4.shared.b16 {%0,%1,%2,%3}, [%4];" \
        : "=r"(r0), "=r"(r1), "=r"(r2), "=r"(r3) : "r"(addr))

__global__ void __launch_bounds__(256, 2)
tc_gemm2(const __nv_bfloat16* __restrict__ Ahi, const __nv_bfloat16* __restrict__ Alo,
         const __nv_bfloat16* __restrict__ Whi, const __nv_bfloat16* __restrict__ Wlo,
         const float* __restrict__ bias, float* __restrict__ C, __half* __restrict__ Ch,
         const int* __restrict__ mlens,
         int N, int Kp, int NC, int ldc)
{
    extern __shared__ __align__(1024) char smem[];
    const uint32_t sbu = smem_to_u32(smem);
    float* bsm = reinterpret_cast<float*>(smem + 2 * STAGE_BYTES);

    const int tid = threadIdx.x;
    const int lane = tid & 31, wid = tid >> 5;
    const int wm = wid & 3, wn = wid >> 2;
    const int m0 = blockIdx.y * 128;
    const int n0 = blockIdx.x * 128;

    const int rem = (N - n0) - wn * 64;
    const int ntmax = (rem >= 64) ? 8 : ((rem <= 0) ? 0 : ((rem + 7) >> 3));
    const int npair = (ntmax + 1) >> 1;

    const int crow = tid >> 2;
    const int cq = (tid & 3) * 8;
    const __nv_bfloat16* sAh0 = Ahi + (size_t)(m0 + crow) * Kp + cq;
    const __nv_bfloat16* sAh1 = Ahi + (size_t)(m0 + crow + 64) * Kp + cq;
    const __nv_bfloat16* sAl0 = Alo + (size_t)(m0 + crow) * Kp + cq;
    const __nv_bfloat16* sAl1 = Alo + (size_t)(m0 + crow + 64) * Kp + cq;
    const __nv_bfloat16* sWh0 = Whi + (size_t)(n0 + crow) * Kp + cq;
    const __nv_bfloat16* sWh1 = Whi + (size_t)(n0 + crow + 64) * Kp + cq;
    const __nv_bfloat16* sWl0 = Wlo + (size_t)(n0 + crow) * Kp + cq;
    const __nv_bfloat16* sWl1 = Wlo + (size_t)(n0 + crow + 64) * Kp + cq;
    const uint32_t doff0 = (uint32_t)((crow * LDK + cq) * 2);
    const uint32_t doff1 = (uint32_t)(((crow + 64) * LDK + cq) * 2);

    const int ro = lane & 15;
    const int khalf = (lane >> 4) << 3;
    const uint32_t aoff0 = (uint32_t)(((wm * 32 + ro) * LDK + khalf) * 2);
    const uint32_t aoff1 = aoff0 + 16 * LDK * 2;
    uint32_t boff[4];
    #pragma unroll
    for (int p = 0; p < 4; p++)
        boff[p] = (uint32_t)(((wn * 64 + p * 16 + ro) * LDK + khalf) * 2);

    if (tid < 128) bsm[tid] = (n0 + tid < N) ? bias[n0 + tid] : 0.f;

    float acc[2][8][4];
    #pragma unroll
    for (int i = 0; i < 2; i++)
        #pragma unroll
        for (int j = 0; j < 8; j++)
            #pragma unroll
            for (int q = 0; q < 4; q++) acc[i][j][q] = 0.f;

    #define ISSUE_CHUNK(cc, st) do { \
        const int _k0 = (cc) * BKC; \
        const uint32_t _db = sbu + (st) * STAGE_BYTES; \
        cp_async16(_db + OFFB_AHI + doff0, sAh0 + _k0); \
        cp_async16(_db + OFFB_AHI + doff1, sAh1 + _k0); \
        cp_async16(_db + OFFB_ALO + doff0, sAl0 + _k0); \
        cp_async16(_db + OFFB_ALO + doff1, sAl1 + _k0); \
        cp_async16(_db + OFFB_WHI + doff0, sWh0 + _k0); \
        cp_async16(_db + OFFB_WHI + doff1, sWh1 + _k0); \
        cp_async16(_db + OFFB_WLO + doff0, sWl0 + _k0); \
        cp_async16(_db + OFFB_WLO + doff1, sWl1 + _k0); \
    } while (0)

    ISSUE_CHUNK(0, 0);
    CP_COMMIT();

    for (int c = 0; c < NC; c++) {
        if (c + 1 < NC) {
            ISSUE_CHUNK(c + 1, (c + 1) & 1);
            CP_COMMIT();
            CP_WAIT(1);
        } else {
            CP_WAIT(0);
        }
        __syncthreads();

        if (npair > 0) {
            const uint32_t base = sbu + (c & 1) * STAGE_BYTES;
            #pragma unroll
            for (int ks = 0; ks < 2; ks++) {
                const uint32_t kb = base + ks * 32;
                uint32_t ah[2][4], al[2][4];
                LDSM4(ah[0][0], ah[0][1], ah[0][2], ah[0][3], kb + OFFB_AHI + aoff0);
                LDSM4(ah[1][0], ah[1][1], ah[1][2], ah[1][3], kb + OFFB_AHI + aoff1);
                LDSM4(al[0][0], al[0][1], al[0][2], al[0][3], kb + OFFB_ALO + aoff0);
                LDSM4(al[1][0], al[1][1], al[1][2], al[1][3], kb + OFFB_ALO + aoff1);
                #pragma unroll
                for (int p = 0; p < 4; p++) {
                    if (p < npair) {
                        uint32_t u0, u1, u2, u3;
                        LDSM4(u0, u1, u2, u3, kb + OFFB_WHI + boff[p]);
                        uint32_t f0[2] = {u0, u2};
                        uint32_t f1[2] = {u1, u3};
                        MMA16816(acc[0][2*p],   ah[0], f0);
                        MMA16816(acc[1][2*p],   ah[1], f0);
                        MMA16816(acc[0][2*p+1], ah[0], f1);
                        MMA16816(acc[1][2*p+1], ah[1], f1);
                        MMA16816(acc[0][2*p],   al[0], f0);
                        MMA16816(acc[1][2*p],   al[1], f0);
                        MMA16816(acc[0][2*p+1], al[0], f1);
                        MMA16816(acc[1][2*p+1], al[1], f1);
                        LDSM4(u0, u1, u2, u3, kb + OFFB_WLO + boff[p]);
                        uint32_t g0[2] = {u0, u2};
                        uint32_t g1[2] = {u1, u3};
                        MMA16816(acc[0][2*p],   ah[0], g0);
                        MMA16816(acc[1][2*p],   ah[1], g0);
                        MMA16816(acc[0][2*p+1], ah[0], g1);
                        MMA16816(acc[1][2*p+1], ah[1], g1);
                    }
                }
            }
        }
        __syncthreads();
    }

    const int g = lane >> 2, t = lane & 3;
    #pragma unroll
    for (int mt = 0; mt < 2; mt++) {
        int row_a = m0 + wm * 32 + mt * 16 + g;
        int row_b = row_a + 8;
        if (Ch) {
            __half* ca = Ch + (size_t)row_a * ldc;
            __half* cb = Ch + (size_t)row_b * ldc;
            #pragma unroll
            for (int nt = 0; nt < 8; nt++) {
                int lc = wn * 64 + nt * 8 + 2 * t;
                int n = n0 + lc;
                if (n < N) {
                    float b0 = bsm[lc], b1 = bsm[lc + 1];
                    __half2 v0 = __floats2half2_rn(acc[mt][nt][0] + b0, acc[mt][nt][1] + b1);
                    __half2 v1 = __floats2half2_rn(acc[mt][nt][2] + b0, acc[mt][nt][3] + b1);
                    *reinterpret_cast<__half2*>(ca + n) = v0;
                    *reinterpret_cast<__half2*>(cb + n) = v1;
                }
            }
        } else {
            float va = 1.f, vb = 1.f;
            if (mlens) {
                va = ((row_a & (Tt - 1)) < mlens[row_a >> 8]) ? 1.f : 0.f;
                vb = ((row_b & (Tt - 1)) < mlens[row_b >> 8]) ? 1.f : 0.f;
            }
            float* ca = C + (size_t)row_a * ldc;
            float* cb = C + (size_t)row_b * ldc;
            #pragma unroll
            for (int nt = 0; nt < 8; nt++) {
                int lc = wn * 64 + nt * 8 + 2 * t;
                int n = n0 + lc;
                if (n < N) {
                    float b0 = bsm[lc], b1 = bsm[lc + 1];
                    *reinterpret_cast<float2*>(ca + n) = make_float2((acc[mt][nt][0] + b0) * va, (acc[mt][nt][1] + b1) * va);
                    *reinterpret_cast<float2*>(cb + n) = make_float2((acc[mt][nt][2] + b0) * vb, (acc[mt][nt][3] + b1) * vb);
                }
            }
        }
    }
}

// ---------------- per-news MHA pooling (fp16 q|k input) ----------------
#define PEE 402
__global__ void __launch_bounds__(256)
pool_kernel(const float* __restrict__ x2)
{
    extern __shared__ float sm[];
    float* qs = sm;
    float* ks = sm + Ss * PEE;
    float* msm = sm + 2 * Ss * PEE;
    float* wf  = msm + Ss;
    const int n = blockIdx.x;
    const int tid = threadIdx.x;
    const int lane = tid & 31, warp = tid >> 5;

    for (int i = tid; i < Ss * Ee; i += 256) {
        int row = i / Ee, col = i % Ee;
        const __half* src = g_qkh + (size_t)(n * Ss + row) * 800;
        qs[row * PEE + col] = __half2float(src[col]);
        ks[row * PEE + col] = __half2float(src[400 + col]);
    }
    __syncthreads();

    const float scale = rsqrtf((float)DHd);
    const int half = lane >> 4;
    const int kl = lane & 15;

    #pragma unroll
    for (int rep = 0; rep < 2; rep++) {
        const int qi = warp + 8 * rep;
        float accw = 0.f;
        const float* kp_base = ks + kl * PEE;
        const float* qp_base = qs + qi * PEE;
        #pragma unroll
        for (int hh = 0; hh < 10; hh++) {
            int h = 2 * hh + half;
            const float* qp = qp_base + h * DHd;
            const float* kp = kp_base + h * DHd;
            float s = 0.f;
            #pragma unroll
            for (int d = 0; d < DHd; d++) s = fmaf(qp[d], kp[d], s);
            s *= scale;
            float mx = s;
            #pragma unroll
            for (int o = 8; o; o >>= 1) mx = fmaxf(mx, __shfl_xor_sync(0xffffffffu, mx, o));
            float e = expf(s - mx);
            float sum = e;
            #pragma unroll
            for (int o = 8; o; o >>= 1) sum += __shfl_xor_sync(0xffffffffu, sum, o);
            accw += e / (sum * (float)NHd);
        }
        accw += __shfl_xor_sync(0xffffffffu, accw, 16);
        float tot = accw;
        #pragma unroll
        for (int o = 8; o; o >>= 1) tot += __shfl_xor_sync(0xffffffffu, tot, o);
        if (lane == 0) msm[qi] = tot * (1.f / (float)Ss);
    }
    __syncthreads();

    if (warp == 0) {
        float v = (lane < Ss) ? msm[lane] : -1e30f;
        float mx = v;
        #pragma unroll
        for (int o = 8; o; o >>= 1) mx = fmaxf(mx, __shfl_xor_sync(0xffffffffu, mx, o));
        mx = fmaxf(mx, __shfl_xor_sync(0xffffffffu, mx, 16));
        float e = (lane < Ss) ? expf(v - mx) : 0.f;
        float z = e;
        #pragma unroll
        for (int o = 8; o; o >>= 1) z += __shfl_xor_sync(0xffffffffu, z, o);
        z += __shfl_xor_sync(0xffffffffu, z, 16);
        if (lane < Ss) wf[lane] = e / z;
    }
    __syncthreads();

    for (int e = tid; e < Ee; e += 256) {
        float acc = 0.f;
        #pragma unroll
        for (int s = 0; s < Ss; s++)
            acc += wf[s] * x2[(size_t)(n * Ss + s) * Ee + e];
        g_pooled[(size_t)n * Ee + e] = acc;
    }
}

// ---------------- LSTM: cp.async fp16 weight streaming, L-step early exit ----------------
#define LCH2 64
#define LNCH2 4                        // 64,64,64,8
#define LBUF2 (LCH2*HC*8)              // 102400 B
#define LSTM_SMEM2 (2*LBUF2)           // 204800 B

__global__ void __launch_bounds__(256, 1)
lstm_kernel(const int* __restrict__ seq_lens)
{
    extern __shared__ __align__(16) char lsm[];
    __shared__ float h_s[HC];
    __shared__ float c_s[HC];
    const int dir = blockIdx.x & 1;
    const int b = blockIdx.x >> 1;
    const uint2* __restrict__ wp = dir ? g_wpkh_b : g_wpkh_f;
    const int u = threadIdx.x;
    const uint32_t sb0 = smem_to_u32(lsm);
    if (u < HC) { h_s[u] = 0.f; c_s[u] = 0.f; }
    __syncthreads();
    const int L = seq_lens[b];

    for (int t = 0; t < L; t++) {
        const int pos = dir ? (L - 1 - t) : t;
        float a0 = 0.f, a1 = 0.f, a2 = 0.f, a3 = 0.f;
        if (u < HC) {
            const float* xr = g_xg + (size_t)(b * Tt + pos) * 1600 + dir * 800;
            a0 = xr[u]; a1 = xr[HC + u]; a2 = xr[2 * HC + u]; a3 = xr[3 * HC + u];
        }
        // chunk 0 -> buf 0 (6400 16B units)
        {
            #pragma unroll
            for (int r = 0; r < 25; r++) {
                int i = u + r * 256;
                cp_async16(sb0 + (uint32_t)i * 16, wp + 2 * i);
            }
            CP_COMMIT();
        }
        for (int c = 0; c < LNCH2; c++) {
            const int k0 = c * LCH2;
            const int kcnt = (c < 3) ? LCH2 : (HC - 3 * LCH2);   // 64 or 8
            if (c + 1 < LNCH2) {
                const int ncnt = (c + 1 < 3) ? LCH2 : (HC - 3 * LCH2);
                const int units = ncnt * 100;                    // 16B units
                const uint2* src = wp + (size_t)(c + 1) * LCH2 * HC;
                const uint32_t dstb = sb0 + ((c + 1) & 1) * LBUF2;
                for (int i = u; i < units; i += 256)
                    cp_async16(dstb + (uint32_t)i * 16, src + 2 * i);
                CP_COMMIT();
                CP_WAIT(1);
            } else {
                CP_WAIT(0);
            }
            __syncthreads();
            if (u < HC) {
                const uint2* wb = reinterpret_cast<const uint2*>(lsm + (c & 1) * LBUF2);
                #pragma unroll 8
                for (int kk = 0; kk < kcnt; kk++) {
                    float hk = h_s[k0 + kk];
                    uint2 w = wb[kk * HC + u];
                    float2 f0 = __half22float2(*reinterpret_cast<__half2*>(&w.x));
                    float2 f1 = __half22float2(*reinterpret_cast<__half2*>(&w.y));
                    a0 = fmaf(f0.x, hk, a0);
                    a1 = fmaf(f0.y, hk, a1);
                    a2 = fmaf(f1.x, hk, a2);
                    a3 = fmaf(f1.y, hk, a3);
                }
            }
            __syncthreads();
        }
        if (u < HC) {
            float ig = 1.f / (1.f + expf(-a0));
            float fg = 1.f / (1.f + expf(-a1));
            float gg = tanhf(a2);
            float og = 1.f / (1.f + expf(-a3));
            float cc = fg * c_s[u] + ig * gg;
            float hh = og * tanhf(cc);
            c_s[u] = cc; h_s[u] = hh;
            g_h[(size_t)(b * Tt + pos) * Hh + dir * HC + u] = hh;
        }
        __syncthreads();
    }
}

// ---------------- causal attention (prefix softmax-sum) ----------------
__global__ void __launch_bounds__(416)
causal_attn_kernel(const float* __restrict__ Wattn)
{
    __shared__ float ex[Tt];
    __shared__ float rz[Tt];
    int b = blockIdx.x;
    int tid = threadIdx.x;
    int warp = tid >> 5, lane = tid & 31;
    int nw = blockDim.x >> 5;

    for (int s = warp; s < Tt; s += nw) {
        const float* hr = g_h + (size_t)(b * Tt + s) * Hh;
        float d = 0.f;
        for (int j = lane; j < Hh; j += 32) d += hr[j] * Wattn[j];
        #pragma unroll
        for (int o = 16; o; o >>= 1) d += __shfl_down_sync(0xffffffffu, d, o);
        if (lane == 0) ex[s] = d;
    }
    __syncthreads();
    if (tid == 0) {
        float mx = -1e30f;
        for (int s = 0; s < Tt; s++) mx = fmaxf(mx, ex[s]);
        float z = 0.f;
        for (int s = 0; s < Tt; s++) {
            float e = expf(ex[s] - mx);
            z += e;
            ex[s] = e;
            rz[s] = 1.f / z;
        }
    }
    __syncthreads();

    if (tid < Hh) {
        int e = tid;
        float acc = 0.f;
        for (int t = 0; t < Tt; t++) {
            acc += ex[t] * g_h[(size_t)(b * Tt + t) * Hh + e];
            g_cat[(size_t)(b * Tt + t) * (2 * Hh) + e] = acc * rz[t];
        }
    }
}

// ---------------- launch ----------------
static inline void gemm2(cudaStream_t st, const __nv_bfloat16* Ah, const __nv_bfloat16* Al,
                         const __nv_bfloat16* Wh, const __nv_bfloat16* Wl,
                         const float* bias, float* C, __half* Ch, const int* mlens,
                         int M, int N, int Kp, int NC, int ldc)
{
    dim3 grid((N + 127) / 128, M / 128);
    tc_gemm2<<<grid, 256, GEMM_SMEM, st>>>(Ah, Al, Wh, Wl, bias, C, Ch, mlens, N, Kp, NC, ldc);
}

extern "C" void kernel_launch(void* const* d_in, const int* in_sizes, int n_in,
                              void* d_out, int out_size)
{
    const float* x1       = (const float*)d_in[0];
    const float* x2       = (const float*)d_in[1];
    const int*   seq_lens = (const int*)d_in[3];
    const float* w_ih_f   = (const float*)d_in[4];
    const float* w_hh_f   = (const float*)d_in[5];
    const float* b_ih_f   = (const float*)d_in[6];
    const float* b_hh_f   = (const float*)d_in[7];
    const float* w_ih_b   = (const float*)d_in[8];
    const float* w_hh_b   = (const float*)d_in[9];
    const float* b_ih_b   = (const float*)d_in[10];
    const float* b_hh_b   = (const float*)d_in[11];
    const float* w_q      = (const float*)d_in[12];
    const float* b_q      = (const float*)d_in[13];
    const float* w_k      = (const float*)d_in[14];
    const float* b_k      = (const float*)d_in[15];
    const float* w_mlp_mha= (const float*)d_in[16];
    const float* b_mlp_mha= (const float*)d_in[17];
    const float* W_attn   = (const float*)d_in[18];
    const float* w_mlp    = (const float*)d_in[20];
    const float* b_mlp    = (const float*)d_in[21];
    float* out = (float*)d_out;

    float *p_xg, *p_pooled, *p_cat, *p_bqk, *p_bs;
    __half* p_qkh;
    cudaGetSymbolAddress((void**)&p_qkh, g_qkh);
    cudaGetSymbolAddress((void**)&p_xg, g_xg);
    cudaGetSymbolAddress((void**)&p_pooled, g_pooled);
    cudaGetSymbolAddress((void**)&p_cat, g_cat);
    cudaGetSymbolAddress((void**)&p_bqk, g_bqk);
    cudaGetSymbolAddress((void**)&p_bs, g_bsum_cat);

    __nv_bfloat16 *x2h, *x2l, *x1h, *x1l, *plh, *pll, *cth, *ctl;
    __nv_bfloat16 *wqkh, *wqkl, *wihh, *wihl, *wmhah, *wmhal, *wmlph, *wmlpl;
    cudaGetSymbolAddress((void**)&x2h, g_x2h);   cudaGetSymbolAddress((void**)&x2l, g_x2l);
    cudaGetSymbolAddress((void**)&x1h, g_x1h);   cudaGetSymbolAddress((void**)&x1l, g_x1l);
    cudaGetSymbolAddress((void**)&plh, g_plh);   cudaGetSymbolAddress((void**)&pll, g_pll);
    cudaGetSymbolAddress((void**)&cth, g_cth);   cudaGetSymbolAddress((void**)&ctl, g_ctl);
    cudaGetSymbolAddress((void**)&wqkh, g_wqkh); cudaGetSymbolAddress((void**)&wqkl, g_wqkl);
    cudaGetSymbolAddress((void**)&wihh, g_wihh); cudaGetSymbolAddress((void**)&wihl, g_wihl);
    cudaGetSymbolAddress((void**)&wmhah, g_wmhah); cudaGetSymbolAddress((void**)&wmhal, g_wmhal);
    cudaGetSymbolAddress((void**)&wmlph, g_wmlph); cudaGetSymbolAddress((void**)&wmlpl, g_wmlpl);

    cudaFuncSetAttribute(tc_gemm2, cudaFuncAttributeMaxDynamicSharedMemorySize, GEMM_SMEM);
    cudaFuncSetAttribute(lstm_kernel, cudaFuncAttributeMaxDynamicSharedMemorySize, LSTM_SMEM2);
    size_t pool_smem = (size_t)(2 * Ss * PEE + 2 * Ss) * sizeof(float);
    cudaFuncSetAttribute(pool_kernel, cudaFuncAttributeMaxDynamicSharedMemorySize, (int)pool_smem);

    // ---- stream fork: side stream runs the LSTM chain concurrently ----
    cudaStream_t s1;
    cudaStreamCreateWithFlags(&s1, cudaStreamNonBlocking);
    cudaEvent_t evFork, evPrep, evJoin;
    cudaEventCreateWithFlags(&evFork, cudaEventDisableTiming);
    cudaEventCreateWithFlags(&evPrep, cudaEventDisableTiming);
    cudaEventCreateWithFlags(&evJoin, cudaEventDisableTiming);

    cudaEventRecord(evFork, 0);
    cudaStreamWaitEvent(s1, evFork, 0);

    // -- s1: prep -> x1 split -> xg GEMM -> LSTM -> causal attention --
    prep_kernel<<<512, 256, 0, s1>>>(b_ih_f, b_hh_f, b_ih_b, b_hh_b, w_hh_f, w_hh_b,
                                     w_ih_f, w_ih_b, w_q, b_q, w_k, b_k, w_mlp_mha, w_mlp);
    cudaEventRecord(evPrep, s1);
    split_kernel<<<512, 256, 0, s1>>>(x1, x1h, x1l, NBT, Ee, KP1);
    gemm2(s1, x1h, x1l, wihh, wihl, p_bs, p_xg, nullptr, nullptr, NBT, 1600, KP1, 13, 1600);
    lstm_kernel<<<2 * Bb, 256, LSTM_SMEM2, s1>>>(seq_lens);
    causal_attn_kernel<<<Bb, 416, 0, s1>>>(W_attn);
    cudaEventRecord(evJoin, s1);

    // -- s0: x2 split -> q|k GEMM (fp16 out) -> pool -> mha GEMM --
    split_kernel<<<8192, 256>>>(x2, x2h, x2l, NTOK, Ee, KP1);
    cudaStreamWaitEvent(0, evPrep, 0);
    gemm2(0, x2h, x2l, wqkh, wqkl, p_bqk, nullptr, p_qkh, nullptr, NTOK, 800, KP1, 13, 800);
    pool_kernel<<<NBT, 256, pool_smem>>>(x2);
    split_kernel<<<512, 256>>>(p_pooled, plh, pll, NBT, Ee, KP1);
    gemm2(0, plh, pll, wmhah, wmhal, b_mlp_mha, p_cat + Hh, nullptr, nullptr, NBT, Hh, KP1, 13, 2 * Hh);

    // -- join + epilogue (mask fused into out GEMM) --
    cudaStreamWaitEvent(0, evJoin, 0);
    split_kernel<<<1024, 256>>>(p_cat, cth, ctl, NBT, 800, 800);
    gemm2(0, cth, ctl, wmlph, wmlpl, b_mlp, out, nullptr, seq_lens, NBT, Ee, 800, 25, Ee);
}

// round 16
// speedup vs baseline: 1.4724x; 1.1180x over previous
#include <cuda_runtime.h>
#include <cuda_fp16.h>
#include <math.h>
#include <stdint.h>

// ---------------- problem constants ----------------
#define Bb 32
#define Tt 256
#define Ss 16
#define Ee 400
#define Hh 400
#define HC 200
#define NHd 20
#define DHd 20
#define NTOK (Bb*Tt*Ss)   // 131072
#define NBT  (Bb*Tt)      // 8192
#define KP1 416           // padded K for K=400 (13 chunks of 32)

// ---------------- scratch ----------------
__device__ __half g_qkh[(size_t)NTOK*800];   // fp16 q|k
__device__ float g_xg[(size_t)NBT*1600];
__device__ float g_pooled[(size_t)NBT*Ee];
__device__ float g_h[(size_t)NBT*Hh];        // zero-init; rows t>=L stay 0
__device__ float g_cat[(size_t)NBT*2*Hh];
__device__ uint2 g_wpkh_f[HC*HC];            // fp16 packed w_hh
__device__ uint2 g_wpkh_b[HC*HC];
__device__ float g_bqk[800];
__device__ float g_bsum_cat[1600];

// ---------------- fp16 planes: activations hi+lo, weights single (zero-init) ----------------
__device__ __half g_x2h[(size_t)NTOK*KP1];
__device__ __half g_x2l[(size_t)NTOK*KP1];
__device__ __half g_x1h[(size_t)NBT*KP1];
__device__ __half g_x1l[(size_t)NBT*KP1];
__device__ __half g_plh[(size_t)NBT*KP1];
__device__ __half g_pll[(size_t)NBT*KP1];
__device__ __half g_cth[(size_t)NBT*800];
__device__ __half g_ctl[(size_t)NBT*800];
__device__ __half g_wqk16[896*KP1];
__device__ __half g_wih16[1664*KP1];
__device__ __half g_wmha16[512*KP1];
__device__ __half g_wmlp16[512*800];

// =================== common helpers ===================
__device__ __forceinline__ uint32_t smem_to_u32(const void* p) {
    uint32_t a;
    asm("{ .reg .u64 t; cvta.to.shared.u64 t, %1; cvt.u32.u64 %0, t; }" : "=r"(a) : "l"(p));
    return a;
}
__device__ __forceinline__ void cp_async16(uint32_t saddr, const void* gaddr) {
    asm volatile("cp.async.cg.shared.global [%0], [%1], 16;" :: "r"(saddr), "l"(gaddr));
}
#define CP_COMMIT() asm volatile("cp.async.commit_group;" ::: "memory")
#define CP_WAIT(n)  asm volatile("cp.async.wait_group %0;" :: "n"(n) : "memory")

__device__ __forceinline__ uint32_t pack_h2(__half a, __half b) {
    __half2 p = __halves2half2(a, b);
    return *reinterpret_cast<uint32_t*>(&p);
}

// fp16 hi/lo split: hi = rn(v), lo = rn(v - hi); hi+lo covers ~22 mantissa bits
__device__ __forceinline__ void split4h_store(float4 v, __half* hp, __half* lp) {
    __half h0 = __float2half_rn(v.x);
    __half h1 = __float2half_rn(v.y);
    __half h2 = __float2half_rn(v.z);
    __half h3 = __float2half_rn(v.w);
    __half l0 = __float2half_rn(v.x - __half2float(h0));
    __half l1 = __float2half_rn(v.y - __half2float(h1));
    __half l2 = __float2half_rn(v.z - __half2float(h2));
    __half l3 = __float2half_rn(v.w - __half2float(h3));
    *reinterpret_cast<uint2*>(hp) = make_uint2(pack_h2(h0, h1), pack_h2(h2, h3));
    *reinterpret_cast<uint2*>(lp) = make_uint2(pack_h2(l0, l1), pack_h2(l2, l3));
}

__device__ __forceinline__ void cvt4h_store(float4 v, __half* p) {
    *reinterpret_cast<uint2*>(p) = make_uint2(
        pack_h2(__float2half_rn(v.x), __float2half_rn(v.y)),
        pack_h2(__float2half_rn(v.z), __float2half_rn(v.w)));
}

// =================== split: fp32 -> fp16 hi/lo planes ===================
__global__ void split_kernel(const float* __restrict__ src, __half* __restrict__ dh,
                             __half* __restrict__ dl, int M, int K, int Kp)
{
    const int kq = K >> 2;
    const int nv = M * kq;
    for (int i = blockIdx.x * blockDim.x + threadIdx.x; i < nv; i += gridDim.x * blockDim.x) {
        int row = i / kq;
        int c4 = (i - row * kq) * 4;
        float4 v = reinterpret_cast<const float4*>(src)[i];
        size_t off = (size_t)row * Kp + c4;
        split4h_store(v, dh + off, dl + off);
    }
}

// =================== prep: biases + fp16 packed w_hh + fp16 weight planes ===================
__global__ void prep_kernel(const float* __restrict__ b_ih_f, const float* __restrict__ b_hh_f,
                            const float* __restrict__ b_ih_b, const float* __restrict__ b_hh_b,
                            const float* __restrict__ w_hh_f, const float* __restrict__ w_hh_b,
                            const float* __restrict__ w_ih_f, const float* __restrict__ w_ih_b,
                            const float* __restrict__ w_q,   const float* __restrict__ b_q,
                            const float* __restrict__ w_k,   const float* __restrict__ b_k,
                            const float* __restrict__ w_mlp_mha, const float* __restrict__ w_mlp)
{
    const int gt = blockIdx.x * blockDim.x + threadIdx.x;
    const int gs = gridDim.x * blockDim.x;

    if (gt < 800)  g_bqk[gt] = (gt < 400) ? b_q[gt] : b_k[gt - 400];
    if (gt < 1600) g_bsum_cat[gt] = (gt < 800) ? (b_ih_f[gt] + b_hh_f[gt])
                                               : (b_ih_b[gt - 800] + b_hh_b[gt - 800]);

    for (int idx = gt; idx < 800 * 100; idx += gs) {
        int row = idx / 100, q4 = (idx - row * 100) * 4;
        const float* src = (row < 400) ? (w_q + (size_t)row * 400) : (w_k + (size_t)(row - 400) * 400);
        float4 v = *reinterpret_cast<const float4*>(src + q4);
        cvt4h_store(v, g_wqk16 + (size_t)row * KP1 + q4);
    }
    for (int idx = gt; idx < 1600 * 100; idx += gs) {
        int row = idx / 100, q4 = (idx - row * 100) * 4;
        const float* src = (row < 800) ? (w_ih_f + (size_t)row * 400) : (w_ih_b + (size_t)(row - 800) * 400);
        float4 v = *reinterpret_cast<const float4*>(src + q4);
        cvt4h_store(v, g_wih16 + (size_t)row * KP1 + q4);
    }
    for (int idx = gt; idx < 400 * 100; idx += gs) {
        int row = idx / 100, q4 = (idx - row * 100) * 4;
        float4 v = *reinterpret_cast<const float4*>(w_mlp_mha + (size_t)row * 400 + q4);
        cvt4h_store(v, g_wmha16 + (size_t)row * KP1 + q4);
    }
    for (int idx = gt; idx < 400 * 200; idx += gs) {
        int row = idx / 200, q4 = (idx - row * 200) * 4;
        float4 v = *reinterpret_cast<const float4*>(w_mlp + (size_t)row * 800 + q4);
        cvt4h_store(v, g_wmlp16 + (size_t)row * 800 + q4);
    }
    // fp16 packed w_hh for LSTM
    for (int idx = gt; idx < HC * HC; idx += gs) {
        int k = idx / HC, u = idx % HC;
        {
            __half2 p0 = __floats2half2_rn(w_hh_f[(size_t)u * HC + k],          w_hh_f[(size_t)(HC + u) * HC + k]);
            __half2 p1 = __floats2half2_rn(w_hh_f[(size_t)(2*HC + u) * HC + k], w_hh_f[(size_t)(3*HC + u) * HC + k]);
            uint2 w;
            w.x = *reinterpret_cast<uint32_t*>(&p0);
            w.y = *reinterpret_cast<uint32_t*>(&p1);
            g_wpkh_f[idx] = w;
        }
        {
            __half2 p0 = __floats2half2_rn(w_hh_b[(size_t)u * HC + k],          w_hh_b[(size_t)(HC + u) * HC + k]);
            __half2 p1 = __floats2half2_rn(w_hh_b[(size_t)(2*HC + u) * HC + k], w_hh_b[(size_t)(3*HC + u) * HC + k]);
            uint2 w;
            w.x = *reinterpret_cast<uint32_t*>(&p0);
            w.y = *reinterpret_cast<uint32_t*>(&p1);
            g_wpkh_b[idx] = w;
        }
    }
}

// =================== fp16x2 mma.sync GEMM (2-pass), cp.async ===================
#define BKC 32
#define LDK 40
#define TILE_ELE (128*LDK)
#define TILE_B   (TILE_ELE*2)
#define STAGE_BYTES (3*TILE_B)          // AHI, ALO, W
#define GEMM_SMEM (2*STAGE_BYTES + 512)
#define OFFB_AHI 0
#define OFFB_ALO TILE_B
#define OFFB_W   (2*TILE_B)

#define MMA16816(d, a, b) \
    asm volatile("mma.sync.aligned.m16n8k16.row.col.f32.f16.f16.f32 " \
        "{%0,%1,%2,%3}, {%4,%5,%6,%7}, {%8,%9}, {%0,%1,%2,%3};" \
        : "+f"((d)[0]), "+f"((d)[1]), "+f"((d)[2]), "+f"((d)[3]) \
        : "r"((a)[0]), "r"((a)[1]), "r"((a)[2]), "r"((a)[3]), "r"((b)[0]), "r"((b)[1]))

#define LDSM4(r0, r1, r2, r3, addr) \
    asm volatile("ldmatrix.sync.aligned.m8n8.x4.shared.b16 {%0,%1,%2,%3}, [%4];" \
        : "=r"(r0), "=r"(r1), "=r"(r2), "=r"(r3) : "r"(addr))

__global__ void __launch_bounds__(256, 2)
tc_gemm2(const __half* __restrict__ Ahi, const __half* __restrict__ Alo,
         const __half* __restrict__ W16,
         const float* __restrict__ bias, float* __restrict__ C, __half* __restrict__ Ch,
         const int* __restrict__ mlens,
         int N, int Kp, int NC, int ldc)
{
    extern __shared__ __align__(1024) char smem[];
    const uint32_t sbu = smem_to_u32(smem);
    float* bsm = reinterpret_cast<float*>(smem + 2 * STAGE_BYTES);

    const int tid = threadIdx.x;
    const int lane = tid & 31, wid = tid >> 5;
    const int wm = wid & 3, wn = wid >> 2;
    const int m0 = blockIdx.y * 128;
    const int n0 = blockIdx.x * 128;

    const int rem = (N - n0) - wn * 64;
    const int ntmax = (rem >= 64) ? 8 : ((rem <= 0) ? 0 : ((rem + 7) >> 3));
    const int npair = (ntmax + 1) >> 1;

    const int crow = tid >> 2;
    const int cq = (tid & 3) * 8;
    const __half* sAh0 = Ahi + (size_t)(m0 + crow) * Kp + cq;
    const __half* sAh1 = Ahi + (size_t)(m0 + crow + 64) * Kp + cq;
    const __half* sAl0 = Alo + (size_t)(m0 + crow) * Kp + cq;
    const __half* sAl1 = Alo + (size_t)(m0 + crow + 64) * Kp + cq;
    const __half* sW0  = W16 + (size_t)(n0 + crow) * Kp + cq;
    const __half* sW1  = W16 + (size_t)(n0 + crow + 64) * Kp + cq;
    const uint32_t doff0 = (uint32_t)((crow * LDK + cq) * 2);
    const uint32_t doff1 = (uint32_t)(((crow + 64) * LDK + cq) * 2);

    const int ro = lane & 15;
    const int khalf = (lane >> 4) << 3;
    const uint32_t aoff0 = (uint32_t)(((wm * 32 + ro) * LDK + khalf) * 2);
    const uint32_t aoff1 = aoff0 + 16 * LDK * 2;
    uint32_t boff[4];
    #pragma unroll
    for (int p = 0; p < 4; p++)
        boff[p] = (uint32_t)(((wn * 64 + p * 16 + ro) * LDK + khalf) * 2);

    if (tid < 128) bsm[tid] = (n0 + tid < N) ? bias[n0 + tid] : 0.f;

    float acc[2][8][4];
    #pragma unroll
    for (int i = 0; i < 2; i++)
        #pragma unroll
        for (int j = 0; j < 8; j++)
            #pragma unroll
            for (int q = 0; q < 4; q++) acc[i][j][q] = 0.f;

    #define ISSUE_CHUNK(cc, st) do { \
        const int _k0 = (cc) * BKC; \
        const uint32_t _db = sbu + (st) * STAGE_BYTES; \
        cp_async16(_db + OFFB_AHI + doff0, sAh0 + _k0); \
        cp_async16(_db + OFFB_AHI + doff1, sAh1 + _k0); \
        cp_async16(_db + OFFB_ALO + doff0, sAl0 + _k0); \
        cp_async16(_db + OFFB_ALO + doff1, sAl1 + _k0); \
        cp_async16(_db + OFFB_W + doff0, sW0 + _k0); \
        cp_async16(_db + OFFB_W + doff1, sW1 + _k0); \
    } while (0)

    ISSUE_CHUNK(0, 0);
    CP_COMMIT();

    for (int c = 0; c < NC; c++) {
        if (c + 1 < NC) {
            ISSUE_CHUNK(c + 1, (c + 1) & 1);
            CP_COMMIT();
            CP_WAIT(1);
        } else {
            CP_WAIT(0);
        }
        __syncthreads();

        if (npair > 0) {
            const uint32_t base = sbu + (c & 1) * STAGE_BYTES;
            #pragma unroll
            for (int ks = 0; ks < 2; ks++) {
                const uint32_t kb = base + ks * 32;
                uint32_t ah[2][4], al[2][4];
                LDSM4(ah[0][0], ah[0][1], ah[0][2], ah[0][3], kb + OFFB_AHI + aoff0);
                LDSM4(ah[1][0], ah[1][1], ah[1][2], ah[1][3], kb + OFFB_AHI + aoff1);
                LDSM4(al[0][0], al[0][1], al[0][2], al[0][3], kb + OFFB_ALO + aoff0);
                LDSM4(al[1][0], al[1][1], al[1][2], al[1][3], kb + OFFB_ALO + aoff1);
                #pragma unroll
                for (int p = 0; p < 4; p++) {
                    if (p < npair) {
                        uint32_t u0, u1, u2, u3;
                        LDSM4(u0, u1, u2, u3, kb + OFFB_W + boff[p]);
                        uint32_t f0[2] = {u0, u2};
                        uint32_t f1[2] = {u1, u3};
                        MMA16816(acc[0][2*p],   ah[0], f0);
                        MMA16816(acc[1][2*p],   ah[1], f0);
                        MMA16816(acc[0][2*p+1], ah[0], f1);
                        MMA16816(acc[1][2*p+1], ah[1], f1);
                        MMA16816(acc[0][2*p],   al[0], f0);
                        MMA16816(acc[1][2*p],   al[1], f0);
                        MMA16816(acc[0][2*p+1], al[0], f1);
                        MMA16816(acc[1][2*p+1], al[1], f1);
                    }
                }
            }
        }
        __syncthreads();
    }

    const int g = lane >> 2, t = lane & 3;
    #pragma unroll
    for (int mt = 0; mt < 2; mt++) {
        int row_a = m0 + wm * 32 + mt * 16 + g;
        int row_b = row_a + 8;
        if (Ch) {
            __half* ca = Ch + (size_t)row_a * ldc;
            __half* cb = Ch + (size_t)row_b * ldc;
            #pragma unroll
            for (int nt = 0; nt < 8; nt++) {
                int lc = wn * 64 + nt * 8 + 2 * t;
                int n = n0 + lc;
                if (n < N) {
                    float b0 = bsm[lc], b1 = bsm[lc + 1];
                    __half2 v0 = __floats2half2_rn(acc[mt][nt][0] + b0, acc[mt][nt][1] + b1);
                    __half2 v1 = __floats2half2_rn(acc[mt][nt][2] + b0, acc[mt][nt][3] + b1);
                    *reinterpret_cast<__half2*>(ca + n) = v0;
                    *reinterpret_cast<__half2*>(cb + n) = v1;
                }
            }
        } else {
            float va = 1.f, vb = 1.f;
            if (mlens) {
                va = ((row_a & (Tt - 1)) < mlens[row_a >> 8]) ? 1.f : 0.f;
                vb = ((row_b & (Tt - 1)) < mlens[row_b >> 8]) ? 1.f : 0.f;
            }
            float* ca = C + (size_t)row_a * ldc;
            float* cb = C + (size_t)row_b * ldc;
            #pragma unroll
            for (int nt = 0; nt < 8; nt++) {
                int lc = wn * 64 + nt * 8 + 2 * t;
                int n = n0 + lc;
                if (n < N) {
                    float b0 = bsm[lc], b1 = bsm[lc + 1];
                    *reinterpret_cast<float2*>(ca + n) = make_float2((acc[mt][nt][0] + b0) * va, (acc[mt][nt][1] + b1) * va);
                    *reinterpret_cast<float2*>(cb + n) = make_float2((acc[mt][nt][2] + b0) * vb, (acc[mt][nt][3] + b1) * vb);
                }
            }
        }
    }
}

// ---------------- per-news MHA pooling (fp16 q|k input) ----------------
#define PEE 402
__global__ void __launch_bounds__(256)
pool_kernel(const float* __restrict__ x2)
{
    extern __shared__ float sm[];
    float* qs = sm;
    float* ks = sm + Ss * PEE;
    float* msm = sm + 2 * Ss * PEE;
    float* wf  = msm + Ss;
    const int n = blockIdx.x;
    const int tid = threadIdx.x;
    const int lane = tid & 31, warp = tid >> 5;

    for (int i = tid; i < Ss * Ee; i += 256) {
        int row = i / Ee, col = i % Ee;
        const __half* src = g_qkh + (size_t)(n * Ss + row) * 800;
        qs[row * PEE + col] = __half2float(src[col]);
        ks[row * PEE + col] = __half2float(src[400 + col]);
    }
    __syncthreads();

    const float scale = rsqrtf((float)DHd);
    const int half = lane >> 4;
    const int kl = lane & 15;

    #pragma unroll
    for (int rep = 0; rep < 2; rep++) {
        const int qi = warp + 8 * rep;
        float accw = 0.f;
        const float* kp_base = ks + kl * PEE;
        const float* qp_base = qs + qi * PEE;
        #pragma unroll
        for (int hh = 0; hh < 10; hh++) {
            int h = 2 * hh + half;
            const float* qp = qp_base + h * DHd;
            const float* kp = kp_base + h * DHd;
            float s = 0.f;
            #pragma unroll
            for (int d = 0; d < DHd; d++) s = fmaf(qp[d], kp[d], s);
            s *= scale;
            float mx = s;
            #pragma unroll
            for (int o = 8; o; o >>= 1) mx = fmaxf(mx, __shfl_xor_sync(0xffffffffu, mx, o));
            float e = expf(s - mx);
            float sum = e;
            #pragma unroll
            for (int o = 8; o; o >>= 1) sum += __shfl_xor_sync(0xffffffffu, sum, o);
            accw += e / (sum * (float)NHd);
        }
        accw += __shfl_xor_sync(0xffffffffu, accw, 16);
        float tot = accw;
        #pragma unroll
        for (int o = 8; o; o >>= 1) tot += __shfl_xor_sync(0xffffffffu, tot, o);
        if (lane == 0) msm[qi] = tot * (1.f / (float)Ss);
    }
    __syncthreads();

    if (warp == 0) {
        float v = (lane < Ss) ? msm[lane] : -1e30f;
        float mx = v;
        #pragma unroll
        for (int o = 8; o; o >>= 1) mx = fmaxf(mx, __shfl_xor_sync(0xffffffffu, mx, o));
        mx = fmaxf(mx, __shfl_xor_sync(0xffffffffu, mx, 16));
        float e = (lane < Ss) ? expf(v - mx) : 0.f;
        float z = e;
        #pragma unroll
        for (int o = 8; o; o >>= 1) z += __shfl_xor_sync(0xffffffffu, z, o);
        z += __shfl_xor_sync(0xffffffffu, z, 16);
        if (lane < Ss) wf[lane] = e / z;
    }
    __syncthreads();

    for (int e = tid; e < Ee; e += 256) {
        float acc = 0.f;
        #pragma unroll
        for (int s = 0; s < Ss; s++)
            acc += wf[s] * x2[(size_t)(n * Ss + s) * Ee + e];
        g_pooled[(size_t)n * Ee + e] = acc;
    }
}

// ---------------- LSTM: cp.async fp16 weight streaming, L-step early exit ----------------
#define LCH2 64
#define LNCH2 4                        // 64,64,64,8
#define LBUF2 (LCH2*HC*8)              // 102400 B
#define LSTM_SMEM2 (2*LBUF2)           // 204800 B

__global__ void __launch_bounds__(256, 1)
lstm_kernel(const int* __restrict__ seq_lens)
{
    extern __shared__ __align__(16) char lsm[];
    __shared__ float h_s[HC];
    __shared__ float c_s[HC];
    const int dir = blockIdx.x & 1;
    const int b = blockIdx.x >> 1;
    const uint2* __restrict__ wp = dir ? g_wpkh_b : g_wpkh_f;
    const int u = threadIdx.x;
    const uint32_t sb0 = smem_to_u32(lsm);
    if (u < HC) { h_s[u] = 0.f; c_s[u] = 0.f; }
    __syncthreads();
    const int L = seq_lens[b];

    for (int t = 0; t < L; t++) {
        const int pos = dir ? (L - 1 - t) : t;
        float a0 = 0.f, a1 = 0.f, a2 = 0.f, a3 = 0.f;
        if (u < HC) {
            const float* xr = g_xg + (size_t)(b * Tt + pos) * 1600 + dir * 800;
            a0 = xr[u]; a1 = xr[HC + u]; a2 = xr[2 * HC + u]; a3 = xr[3 * HC + u];
        }
        {
            #pragma unroll
            for (int r = 0; r < 25; r++) {
                int i = u + r * 256;
                cp_async16(sb0 + (uint32_t)i * 16, wp + 2 * i);
            }
            CP_COMMIT();
        }
        for (int c = 0; c < LNCH2; c++) {
            const int k0 = c * LCH2;
            const int kcnt = (c < 3) ? LCH2 : (HC - 3 * LCH2);
            if (c + 1 < LNCH2) {
                const int ncnt = (c + 1 < 3) ? LCH2 : (HC - 3 * LCH2);
                const int units = ncnt * 100;
                const uint2* src = wp + (size_t)(c + 1) * LCH2 * HC;
                const uint32_t dstb = sb0 + ((c + 1) & 1) * LBUF2;
                for (int i = u; i < units; i += 256)
                    cp_async16(dstb + (uint32_t)i * 16, src + 2 * i);
                CP_COMMIT();
                CP_WAIT(1);
            } else {
                CP_WAIT(0);
            }
            __syncthreads();
            if (u < HC) {
                const uint2* wb = reinterpret_cast<const uint2*>(lsm + (c & 1) * LBUF2);
                #pragma unroll 8
                for (int kk = 0; kk < kcnt; kk++) {
                    float hk = h_s[k0 + kk];
                    uint2 w = wb[kk * HC + u];
                    float2 f0 = __half22float2(*reinterpret_cast<__half2*>(&w.x));
                    float2 f1 = __half22float2(*reinterpret_cast<__half2*>(&w.y));
                    a0 = fmaf(f0.x, hk, a0);
                    a1 = fmaf(f0.y, hk, a1);
                    a2 = fmaf(f1.x, hk, a2);
                    a3 = fmaf(f1.y, hk, a3);
                }
            }
            __syncthreads();
        }
        if (u < HC) {
            float ig = 1.f / (1.f + expf(-a0));
            float fg = 1.f / (1.f + expf(-a1));
            float gg = tanhf(a2);
            float og = 1.f / (1.f + expf(-a3));
            float cc = fg * c_s[u] + ig * gg;
            float hh = og * tanhf(cc);
            c_s[u] = cc; h_s[u] = hh;
            g_h[(size_t)(b * Tt + pos) * Hh + dir * HC + u] = hh;
        }
        __syncthreads();
    }
}

// ---------------- causal attention (prefix softmax-sum) ----------------
__global__ void __launch_bounds__(416)
causal_attn_kernel(const float* __restrict__ Wattn)
{
    __shared__ float ex[Tt];
    __shared__ float rz[Tt];
    int b = blockIdx.x;
    int tid = threadIdx.x;
    int warp = tid >> 5, lane = tid & 31;
    int nw = blockDim.x >> 5;

    for (int s = warp; s < Tt; s += nw) {
        const float* hr = g_h + (size_t)(b * Tt + s) * Hh;
        float d = 0.f;
        for (int j = lane; j < Hh; j += 32) d += hr[j] * Wattn[j];
        #pragma unroll
        for (int o = 16; o; o >>= 1) d += __shfl_down_sync(0xffffffffu, d, o);
        if (lane == 0) ex[s] = d;
    }
    __syncthreads();
    if (tid == 0) {
        float mx = -1e30f;
        for (int s = 0; s < Tt; s++) mx = fmaxf(mx, ex[s]);
        float z = 0.f;
        for (int s = 0; s < Tt; s++) {
            float e = expf(ex[s] - mx);
            z += e;
            ex[s] = e;
            rz[s] = 1.f / z;
        }
    }
    __syncthreads();

    if (tid < Hh) {
        int e = tid;
        float acc = 0.f;
        for (int t = 0; t < Tt; t++) {
            acc += ex[t] * g_h[(size_t)(b * Tt + t) * Hh + e];
            g_cat[(size_t)(b * Tt + t) * (2 * Hh) + e] = acc * rz[t];
        }
    }
}

// ---------------- launch ----------------
static inline void gemm2(cudaStream_t st, const __half* Ah, const __half* Al, const __half* W16,
                         const float* bias, float* C, __half* Ch, const int* mlens,
                         int M, int N, int Kp, int NC, int ldc)
{
    dim3 grid((N + 127) / 128, M / 128);
    tc_gemm2<<<grid, 256, GEMM_SMEM, st>>>(Ah, Al, W16, bias, C, Ch, mlens, N, Kp, NC, ldc);
}

extern "C" void kernel_launch(void* const* d_in, const int* in_sizes, int n_in,
                              void* d_out, int out_size)
{
    const float* x1       = (const float*)d_in[0];
    const float* x2       = (const float*)d_in[1];
    const int*   seq_lens = (const int*)d_in[3];
    const float* w_ih_f   = (const float*)d_in[4];
    const float* w_hh_f   = (const float*)d_in[5];
    const float* b_ih_f   = (const float*)d_in[6];
    const float* b_hh_f   = (const float*)d_in[7];
    const float* w_ih_b   = (const float*)d_in[8];
    const float* w_hh_b   = (const float*)d_in[9];
    const float* b_ih_b   = (const float*)d_in[10];
    const float* b_hh_b   = (const float*)d_in[11];
    const float* w_q      = (const float*)d_in[12];
    const float* b_q      = (const float*)d_in[13];
    const float* w_k      = (const float*)d_in[14];
    const float* b_k      = (const float*)d_in[15];
    const float* w_mlp_mha= (const float*)d_in[16];
    const float* b_mlp_mha= (const float*)d_in[17];
    const float* W_attn   = (const float*)d_in[18];
    const float* w_mlp    = (const float*)d_in[20];
    const float* b_mlp    = (const float*)d_in[21];
    float* out = (float*)d_out;

    float *p_xg, *p_pooled, *p_cat, *p_bqk, *p_bs;
    __half* p_qkh;
    cudaGetSymbolAddress((void**)&p_qkh, g_qkh);
    cudaGetSymbolAddress((void**)&p_xg, g_xg);
    cudaGetSymbolAddress((void**)&p_pooled, g_pooled);
    cudaGetSymbolAddress((void**)&p_cat, g_cat);
    cudaGetSymbolAddress((void**)&p_bqk, g_bqk);
    cudaGetSymbolAddress((void**)&p_bs, g_bsum_cat);

    __half *x2h, *x2l, *x1h, *x1l, *plh, *pll, *cth, *ctl;
    __half *wqk16, *wih16, *wmha16, *wmlp16;
    cudaGetSymbolAddress((void**)&x2h, g_x2h);   cudaGetSymbolAddress((void**)&x2l, g_x2l);
    cudaGetSymbolAddress((void**)&x1h, g_x1h);   cudaGetSymbolAddress((void**)&x1l, g_x1l);
    cudaGetSymbolAddress((void**)&plh, g_plh);   cudaGetSymbolAddress((void**)&pll, g_pll);
    cudaGetSymbolAddress((void**)&cth, g_cth);   cudaGetSymbolAddress((void**)&ctl, g_ctl);
    cudaGetSymbolAddress((void**)&wqk16, g_wqk16);
    cudaGetSymbolAddress((void**)&wih16, g_wih16);
    cudaGetSymbolAddress((void**)&wmha16, g_wmha16);
    cudaGetSymbolAddress((void**)&wmlp16, g_wmlp16);

    cudaFuncSetAttribute(tc_gemm2, cudaFuncAttributeMaxDynamicSharedMemorySize, GEMM_SMEM);
    cudaFuncSetAttribute(lstm_kernel, cudaFuncAttributeMaxDynamicSharedMemorySize, LSTM_SMEM2);
    size_t pool_smem = (size_t)(2 * Ss * PEE + 2 * Ss) * sizeof(float);
    cudaFuncSetAttribute(pool_kernel, cudaFuncAttributeMaxDynamicSharedMemorySize, (int)pool_smem);

    // ---- stream fork: side stream runs the LSTM chain concurrently ----
    cudaStream_t s1;
    cudaStreamCreateWithFlags(&s1, cudaStreamNonBlocking);
    cudaEvent_t evFork, evPrep, evJoin;
    cudaEventCreateWithFlags(&evFork, cudaEventDisableTiming);
    cudaEventCreateWithFlags(&evPrep, cudaEventDisableTiming);
    cudaEventCreateWithFlags(&evJoin, cudaEventDisableTiming);

    cudaEventRecord(evFork, 0);
    cudaStreamWaitEvent(s1, evFork, 0);

    // -- s1: prep -> x1 split -> xg GEMM -> LSTM -> causal attention --
    prep_kernel<<<512, 256, 0, s1>>>(b_ih_f, b_hh_f, b_ih_b, b_hh_b, w_hh_f, w_hh_b,
                                     w_ih_f, w_ih_b, w_q, b_q, w_k, b_k, w_mlp_mha, w_mlp);
    cudaEventRecord(evPrep, s1);
    split_kernel<<<512, 256, 0, s1>>>(x1, x1h, x1l, NBT, Ee, KP1);
    gemm2(s1, x1h, x1l, wih16, p_bs, p_xg, nullptr, nullptr, NBT, 1600, KP1, 13, 1600);
    lstm_kernel<<<2 * Bb, 256, LSTM_SMEM2, s1>>>(seq_lens);
    causal_attn_kernel<<<Bb, 416, 0, s1>>>(W_attn);
    cudaEventRecord(evJoin, s1);

    // -- s0: x2 split -> q|k GEMM (fp16 out) -> pool -> mha GEMM --
    split_kernel<<<8192, 256>>>(x2, x2h, x2l, NTOK, Ee, KP1);
    cudaStreamWaitEvent(0, evPrep, 0);
    gemm2(0, x2h, x2l, wqk16, p_bqk, nullptr, p_qkh, nullptr, NTOK, 800, KP1, 13, 800);
    pool_kernel<<<NBT, 256, pool_smem>>>(x2);
    split_kernel<<<512, 256>>>(p_pooled, plh, pll, NBT, Ee, KP1);
    gemm2(0, plh, pll, wmha16, b_mlp_mha, p_cat + Hh, nullptr, nullptr, NBT, Hh, KP1, 13, 2 * Hh);

    // -- join + epilogue (mask fused into out GEMM) --
    cudaStreamWaitEvent(0, evJoin, 0);
    split_kernel<<<1024, 256>>>(p_cat, cth, ctl, NBT, 800, 800);
    gemm2(0, cth, ctl, wmlp16, b_mlp, out, nullptr, seq_lens, NBT, Ee, 800, 25, Ee);
}